// round 2
// baseline (speedup 1.0000x reference)
#include <cuda_runtime.h>

// ---------------------------------------------------------------------------
// ScatLayerj2: 2-level DTCWT scattering.
// x (32,3,512,512) f32 -> Z (32,147,128,128) f32
// ---------------------------------------------------------------------------

static __device__ __forceinline__ int refl(int p, int l) {
    if (p < 0)  p = -1 - p;
    if (p >= l) p = 2 * l - 1 - p;
    return p;
}

static __device__ __forceinline__ float smag(float re, float im) {
    return sqrtf(re * re + im * im + 1e-4f) - 0.01f;
}

// q2c of a 2x2 block (v[0]=row0 {col0,col1}, v[1]=row1) -> two magnitudes
static __device__ __forceinline__ void q2c_mags(const float2 v0, const float2 v1,
                                                float& m_first, float& m_second) {
    const float s = 0.70710678118654752440f;
    float a = v0.x * s, b = v0.y * s, c = v1.x * s, d = v1.y * s;
    m_first  = smag(a - d, b + c);
    m_second = smag(a + d, b - c);
}

// Scratch (reused across stages):
// g_lo/g_hi: lo/hi (25.2M), lo2/hi2 (12.6M), lo3/hi3 (37.7M)
// g_ll: ll of stage A (25.2M)   g_p: p = s1_j1 reshaped (37.7M)
__device__ float g_lo[37748736];
__device__ float g_hi[37748736];
__device__ float g_ll[25165824];
__device__ float g_p [37748736];

// ---------------------------------------------------------------------------
// K1/K6: row filtering with h0o (5-tap) and h1o (7-tap), symmetric pad.
// in: (nimg, W, W) square images. Writes both lo and hi.
// ---------------------------------------------------------------------------
__global__ void k_rowfilter2(const float* __restrict__ in,
                             float* __restrict__ olo, float* __restrict__ ohi,
                             const float* __restrict__ h0, const float* __restrict__ h1,
                             int W, long total)
{
    long i = (long)blockIdx.x * blockDim.x + threadIdx.x;
    if (i >= total) return;
    int x = (int)(i % W);
    const float* row = in + (i - x);
    float f0[5], f1[7];
#pragma unroll
    for (int k = 0; k < 5; k++) f0[k] = __ldg(h0 + k);
#pragma unroll
    for (int k = 0; k < 7; k++) f1[k] = __ldg(h1 + k);
    float s0 = 0.f, s1 = 0.f;
#pragma unroll
    for (int k = 0; k < 7; k++) {
        float v = row[refl(x - 3 + k, W)];
        s1 += f1[k] * v;
        if (k >= 1 && k <= 5) s0 += f0[k - 1] * v;
    }
    olo[i] = s0;
    ohi[i] = s1;
}

// ---------------------------------------------------------------------------
// Shared col-filter block for j1 stages: computes ll/lh/hl/hh at a 2x2 block
// (rows 2Y..2Y+1, cols 2X..2X+1) from lo/hi images of size WxW.
// ---------------------------------------------------------------------------
static __device__ __forceinline__ void j1_col_block(
    const float* __restrict__ L, const float* __restrict__ H,
    int Y, int X, int W, const float* f0, const float* f1,
    float2 vll[2], float2 vlh[2], float2 vhl[2], float2 vhh[2])
{
    vll[0] = vll[1] = vlh[0] = vlh[1] = make_float2(0.f, 0.f);
    vhl[0] = vhl[1] = vhh[0] = vhh[1] = make_float2(0.f, 0.f);
    int col = 2 * X;
#pragma unroll
    for (int r = 0; r < 8; r++) {
        int ry = refl(2 * Y - 3 + r, W);
        float2 l = *(const float2*)(L + (long)ry * W + col);
        float2 h = *(const float2*)(H + (long)ry * W + col);
        if (r <= 6) {            // lh row0: k=r
            float c = f1[r];
            vlh[0].x += c * l.x; vlh[0].y += c * l.y;
            vhh[0].x += c * h.x; vhh[0].y += c * h.y;
        }
        if (r >= 1) {            // lh row1: k=r-1
            float c = f1[r - 1];
            vlh[1].x += c * l.x; vlh[1].y += c * l.y;
            vhh[1].x += c * h.x; vhh[1].y += c * h.y;
        }
        if (r >= 1 && r <= 5) {  // ll row0: k=r-1 in [0,4]
            float c = f0[r - 1];
            vll[0].x += c * l.x; vll[0].y += c * l.y;
            vhl[0].x += c * h.x; vhl[0].y += c * h.y;
        }
        if (r >= 2 && r <= 6) {  // ll row1: k=r-2 in [0,4]
            float c = f0[r - 2];
            vll[1].x += c * l.x; vll[1].y += c * l.y;
            vhl[1].x += c * h.x; vhl[1].y += c * h.y;
        }
    }
}

// ---------------------------------------------------------------------------
// K3: stage-A fused col filter + q2c/mag. in: lo/hi (96,512,512).
// Writes ll (96,512,512) and p laid out as (32, 18=o1*3+ch, 256, 256).
// ---------------------------------------------------------------------------
__global__ void k_stageA(const float* __restrict__ lo, const float* __restrict__ hi,
                         const float* __restrict__ h0, const float* __restrict__ h1,
                         float* __restrict__ ll, float* __restrict__ p)
{
    const long TOT = 96L * 256 * 256;
    long i = (long)blockIdx.x * blockDim.x + threadIdx.x;
    if (i >= TOT) return;
    int X = (int)(i & 255), Y = (int)((i >> 8) & 255), img = (int)(i >> 16);
    int b = img / 3, ch = img - 3 * b;
    float f0[5], f1[7];
#pragma unroll
    for (int k = 0; k < 5; k++) f0[k] = __ldg(h0 + k);
#pragma unroll
    for (int k = 0; k < 7; k++) f1[k] = __ldg(h1 + k);

    const float* L = lo + (long)img * 262144;
    const float* H = hi + (long)img * 262144;
    float2 vll[2], vlh[2], vhl[2], vhh[2];
    j1_col_block(L, H, Y, X, 512, f0, f1, vll, vlh, vhl, vhh);

    float* llp = ll + (long)img * 262144;
    *(float2*)(llp + (long)(2 * Y) * 512 + 2 * X)     = vll[0];
    *(float2*)(llp + (long)(2 * Y + 1) * 512 + 2 * X) = vll[1];

    float m[6];
    q2c_mags(vlh[0], vlh[1], m[0], m[5]);
    q2c_mags(vhh[0], vhh[1], m[1], m[4]);
    q2c_mags(vhl[0], vhl[1], m[2], m[3]);

    float* pb = p + ((long)b * 18 + ch) * 65536 + ((long)Y * 256 + X);
#pragma unroll
    for (int o = 0; o < 6; o++) pb[(long)o * 196608] = m[o];  // o stride = 3*65536
}

// ---------------------------------------------------------------------------
// K4: rowdfilt (both branches) on ll (96,512,512) -> lo2/hi2 (96,512,256).
// lo branch: even col = h0b @ off -8, odd col = h0a @ off -7.
// hi branch: even col = h1a @ off -7, odd col = h1b @ off -8.
// ---------------------------------------------------------------------------
__global__ void k_rowdfilt(const float* __restrict__ in,
                           float* __restrict__ olo, float* __restrict__ ohi,
                           const float* __restrict__ h0a, const float* __restrict__ h0b,
                           const float* __restrict__ h1a, const float* __restrict__ h1b)
{
    const long TOT = 96L * 512 * 256;
    long i = (long)blockIdx.x * blockDim.x + threadIdx.x;
    if (i >= TOT) return;
    int cc = (int)(i & 255);
    long rowid = i >> 8;
    const float* row = in + rowid * 512;
    int odd = cc & 1, ii = cc >> 1;
    int baselo = 4 * ii - (odd ? 7 : 8);
    int basehi = 4 * ii - (odd ? 8 : 7);
    const float* hlo = odd ? h0a : h0b;
    const float* hhi = odd ? h1b : h1a;
    float s = 0.f, t = 0.f;
#pragma unroll
    for (int k = 0; k < 10; k++) {
        s += __ldg(hlo + k) * row[refl(baselo + 2 * k, 512)];
        t += __ldg(hhi + k) * row[refl(basehi + 2 * k, 512)];
    }
    olo[i] = s;
    ohi[i] = t;
}

// ---------------------------------------------------------------------------
// K5: stage-B fused coldfilt + q2c/mag + avgpool(ll2) -> Z slots 0, 7..12.
// in: lo2/hi2 (96,512,256). Output block (Y,X) in 128x128.
// coldfilt rows: even out row = (ha filter on even-offset set, off -8),
//                odd  out row = (hb filter on odd-offset set,  off -7),
// with the highpass swap already folded into which filter hits which set.
// ---------------------------------------------------------------------------
__global__ void k_stageB(const float* __restrict__ lo2, const float* __restrict__ hi2,
                         const float* __restrict__ h0a, const float* __restrict__ h0b,
                         const float* __restrict__ h1a, const float* __restrict__ h1b,
                         float* __restrict__ Z)
{
    const long TOT = 96L * 128 * 128;
    long i = (long)blockIdx.x * blockDim.x + threadIdx.x;
    if (i >= TOT) return;
    int X = (int)(i & 127), Y = (int)((i >> 7) & 127), img = (int)(i >> 14);
    int b = img / 3, ch = img - 3 * b;
    const float* L = lo2 + (long)img * 131072;  // 512*256
    const float* H = hi2 + (long)img * 131072;
    int col = 2 * X;

    float2 ll0 = {0,0}, ll1 = {0,0}, lh0 = {0,0}, lh1 = {0,0};
    float2 hl0 = {0,0}, hl1 = {0,0}, hh0 = {0,0}, hh1 = {0,0};
#pragma unroll
    for (int k = 0; k < 10; k++) {
        int rE = refl(4 * Y + 2 * k - 8, 512);
        int rO = refl(4 * Y + 2 * k - 7, 512);
        float2 a = *(const float2*)(L + (long)rE * 256 + col);
        float2 q = *(const float2*)(L + (long)rO * 256 + col);
        float2 c = *(const float2*)(H + (long)rE * 256 + col);
        float2 d = *(const float2*)(H + (long)rO * 256 + col);
        float c0b = __ldg(h0b + k), c0a = __ldg(h0a + k);
        float c1a = __ldg(h1a + k), c1b = __ldg(h1b + k);
        // ll2: even row = h0b·even-set, odd row = h0a·odd-set
        ll0.x += c0b * a.x; ll0.y += c0b * a.y;
        ll1.x += c0a * q.x; ll1.y += c0a * q.y;
        // lh2 (highpass): even row = h1a·odd-set, odd row = h1b·even-set
        lh0.x += c1a * q.x; lh0.y += c1a * q.y;
        lh1.x += c1b * a.x; lh1.y += c1b * a.y;
        // hl2: lowpass rows on hi branch
        hl0.x += c0b * c.x; hl0.y += c0b * c.y;
        hl1.x += c0a * d.x; hl1.y += c0a * d.y;
        // hh2: highpass rows on hi branch
        hh0.x += c1a * d.x; hh0.y += c1a * d.y;
        hh1.x += c1b * c.x; hh1.y += c1b * c.y;
    }

    float s0v = 0.25f * (ll0.x + ll0.y + ll1.x + ll1.y);
    float m[6];
    q2c_mags(lh0, lh1, m[0], m[5]);
    q2c_mags(hh0, hh1, m[1], m[4]);
    q2c_mags(hl0, hl1, m[2], m[3]);

    // Z layout (b, 49, 3, 128, 128): base = (b*147 + ch)*16384 + pix; slot stride 49152
    float* zb = Z + ((long)b * 147 + ch) * 16384 + ((long)Y * 128 + X);
    zb[0] = s0v;                     // slot 0
#pragma unroll
    for (int o = 0; o < 6; o++) zb[(long)(7 + o) * 49152] = m[o];  // slots 7..12
}

// ---------------------------------------------------------------------------
// K7: stage-C fused col filter + q2c/mag + avgpool(p_ll).
// in: lo3/hi3 (576,256,256) where 576 = b*18 + (o1*3+ch).
// Writes Z slots 1..6 (avgpool of ll3) and 13..48 (s2 mags).
// ---------------------------------------------------------------------------
__global__ void k_stageC(const float* __restrict__ lo3, const float* __restrict__ hi3,
                         const float* __restrict__ h0, const float* __restrict__ h1,
                         float* __restrict__ Z)
{
    const long TOT = 576L * 128 * 128;
    long i = (long)blockIdx.x * blockDim.x + threadIdx.x;
    if (i >= TOT) return;
    int X = (int)(i & 127), Y = (int)((i >> 7) & 127), img = (int)(i >> 14);
    int b = img / 18;
    int c18 = img - 18 * b;
    int o1 = c18 / 3;
    int ch = c18 - 3 * o1;
    float f0[5], f1[7];
#pragma unroll
    for (int k = 0; k < 5; k++) f0[k] = __ldg(h0 + k);
#pragma unroll
    for (int k = 0; k < 7; k++) f1[k] = __ldg(h1 + k);

    const float* L = lo3 + (long)img * 65536;
    const float* H = hi3 + (long)img * 65536;
    float2 vll[2], vlh[2], vhl[2], vhh[2];
    j1_col_block(L, H, Y, X, 256, f0, f1, vll, vlh, vhl, vhh);

    float avg = 0.25f * (vll[0].x + vll[0].y + vll[1].x + vll[1].y);
    float m[6];
    q2c_mags(vlh[0], vlh[1], m[0], m[5]);
    q2c_mags(vhh[0], vhh[1], m[1], m[4]);
    q2c_mags(vhl[0], vhl[1], m[2], m[3]);

    float* zb = Z + ((long)b * 147 + ch) * 16384 + ((long)Y * 128 + X);
    zb[(long)(1 + o1) * 49152] = avg;                 // slots 1..6
#pragma unroll
    for (int o2 = 0; o2 < 6; o2++)
        zb[(long)(13 + o2 * 6 + o1) * 49152] = m[o2]; // slots 13..48
}

// ---------------------------------------------------------------------------
// Host: launch pipeline (graph-capturable, no allocations, no syncs)
// ---------------------------------------------------------------------------
extern "C" void kernel_launch(void* const* d_in, const int* in_sizes, int n_in,
                              void* d_out, int out_size)
{
    const float* x   = (const float*)d_in[0];
    const float* h0o = (const float*)d_in[1];
    const float* h1o = (const float*)d_in[2];
    const float* h0a = (const float*)d_in[3];
    const float* h0b = (const float*)d_in[4];
    const float* h1a = (const float*)d_in[5];
    const float* h1b = (const float*)d_in[6];
    float* Z = (float*)d_out;

    float *lo, *hi, *ll, *p;
    cudaGetSymbolAddress((void**)&lo, g_lo);
    cudaGetSymbolAddress((void**)&hi, g_hi);
    cudaGetSymbolAddress((void**)&ll, g_ll);
    cudaGetSymbolAddress((void**)&p,  g_p);

    const int B = 256;

    // Stage A: fwd_j1 on x
    { long t = 25165824; k_rowfilter2<<<(int)((t + B - 1) / B), B>>>(x, lo, hi, h0o, h1o, 512, t); }
    { long t = 6291456;  k_stageA<<<(int)((t + B - 1) / B), B>>>(lo, hi, h0o, h1o, ll, p); }

    // Stage B: fwd_j2plus on ll -> Z slots 0, 7..12
    { long t = 12582912; k_rowdfilt<<<(int)((t + B - 1) / B), B>>>(ll, lo, hi, h0a, h0b, h1a, h1b); }
    { long t = 1572864;  k_stageB<<<(int)((t + B - 1) / B), B>>>(lo, hi, h0a, h0b, h1a, h1b, Z); }

    // Stage C: fwd_j1 on p -> Z slots 1..6, 13..48
    { long t = 37748736; k_rowfilter2<<<(int)((t + B - 1) / B), B>>>(p, lo, hi, h0o, h1o, 256, t); }
    { long t = 9437184;  k_stageC<<<(int)((t + B - 1) / B), B>>>(lo, hi, h0o, h1o, Z); }
}

// round 4
// speedup vs baseline: 1.3919x; 1.3919x over previous
#include <cuda_runtime.h>

// ---------------------------------------------------------------------------
// ScatLayerj2: 2-level DTCWT scattering, fully fused per stage.
// x (32,3,512,512) f32 -> Z (32,147,128,128) f32
// ---------------------------------------------------------------------------

static __device__ __forceinline__ int refl(int p, int l) {
    if (p < 0)  p = -1 - p;
    if (p >= l) p = 2 * l - 1 - p;
    return p;
}

static __device__ __forceinline__ float smag(float re, float im) {
    return sqrtf(re * re + im * im + 1e-4f) - 0.01f;
}

static __device__ __forceinline__ void q2c_mags(float v0x, float v0y, float v1x, float v1y,
                                                float& m_first, float& m_second) {
    const float s = 0.70710678118654752440f;
    float a = v0x * s, b = v0y * s, c = v1x * s, d = v1y * s;
    m_first  = smag(a - d, b + c);
    m_second = smag(a + d, b - c);
}

// Scratch: ll (96*512*512) and p (576*256*256)
__device__ float g_ll[25165824];
__device__ float g_p [37748736];

// ---------------------------------------------------------------------------
// Stage A: fused rowfilter(h0o,h1o) + colfilter + q2c/mag on x.
// Block (32,8): out block coords Y=8*by+ty (0..255), X=32*bx+tx (0..255).
// Writes ll (96,512,512) and p (32, 18=3*o1+ch, 256, 256).
// ---------------------------------------------------------------------------
__global__ __launch_bounds__(256) void k_fusedA(
    const float* __restrict__ x,
    const float* __restrict__ h0, const float* __restrict__ h1,
    float* __restrict__ ll, float* __restrict__ p)
{
    __shared__ float sx [22][72];   // x tile: rows [16by-3,16by+18], cols [64bx-3,64bx+66]
    __shared__ float slo[22][64];
    __shared__ float shi[22][64];

    const int bx = blockIdx.x, by = blockIdx.y, img = blockIdx.z;
    const int tx = threadIdx.x, ty = threadIdx.y;
    const int tid = ty * 32 + tx;
    const int W = 512;
    const float* xim = x + (long)img * W * W;
    const int r0 = 16 * by - 3;
    const int c0 = 64 * bx - 3;

    float f0[5], f1[7];
#pragma unroll
    for (int k = 0; k < 5; k++) f0[k] = __ldg(h0 + k);
#pragma unroll
    for (int k = 0; k < 7; k++) f1[k] = __ldg(h1 + k);

    for (int idx = tid; idx < 22 * 70; idx += 256) {
        int rr = idx / 70, cc = idx - rr * 70;
        sx[rr][cc] = xim[(long)refl(r0 + rr, W) * W + refl(c0 + cc, W)];
    }
    __syncthreads();

    // row filter: 22 rows x 64 cols. out col cc -> x local cols cc..cc+6
    for (int idx = tid; idx < 22 * 64; idx += 256) {
        int rr = idx >> 6, cc = idx & 63;
        float s1 = 0.f;
#pragma unroll
        for (int k = 0; k < 7; k++) s1 += f1[k] * sx[rr][cc + k];
        float s0 = 0.f;
#pragma unroll
        for (int k = 0; k < 5; k++) s0 += f0[k] * sx[rr][cc + 1 + k];
        slo[rr][cc] = s0;
        shi[rr][cc] = s1;
    }
    __syncthreads();

    // col filter at 2x2 block (2Y..2Y+1, 2X..2X+1); local rows 2ty..2ty+7, cols 2tx,2tx+1
    float vll0x=0,vll0y=0,vll1x=0,vll1y=0, vlh0x=0,vlh0y=0,vlh1x=0,vlh1y=0;
    float vhl0x=0,vhl0y=0,vhl1x=0,vhl1y=0, vhh0x=0,vhh0y=0,vhh1x=0,vhh1y=0;
#pragma unroll
    for (int r = 0; r < 8; r++) {
        int lr = 2 * ty + r;
        float lx = slo[lr][2*tx], ly = slo[lr][2*tx+1];
        float hx = shi[lr][2*tx], hy = shi[lr][2*tx+1];
        if (r <= 6) { float c = f1[r];
            vlh0x += c*lx; vlh0y += c*ly; vhh0x += c*hx; vhh0y += c*hy; }
        if (r >= 1) { float c = f1[r-1];
            vlh1x += c*lx; vlh1y += c*ly; vhh1x += c*hx; vhh1y += c*hy; }
        if (r >= 1 && r <= 5) { float c = f0[r-1];
            vll0x += c*lx; vll0y += c*ly; vhl0x += c*hx; vhl0y += c*hy; }
        if (r >= 2 && r <= 6) { float c = f0[r-2];
            vll1x += c*lx; vll1y += c*ly; vhl1x += c*hx; vhl1y += c*hy; }
    }

    const int Y = 8 * by + ty, X = 32 * bx + tx;
    float* llp = ll + (long)img * 262144;
    *(float2*)(llp + (long)(2 * Y) * 512 + 2 * X)     = make_float2(vll0x, vll0y);
    *(float2*)(llp + (long)(2 * Y + 1) * 512 + 2 * X) = make_float2(vll1x, vll1y);

    float m[6];
    q2c_mags(vlh0x, vlh0y, vlh1x, vlh1y, m[0], m[5]);
    q2c_mags(vhh0x, vhh0y, vhh1x, vhh1y, m[1], m[4]);
    q2c_mags(vhl0x, vhl0y, vhl1x, vhl1y, m[2], m[3]);

    int b = img / 3, ch = img - 3 * b;
    float* pb = p + ((long)b * 18 + ch) * 65536 + ((long)Y * 256 + X);
#pragma unroll
    for (int o = 0; o < 6; o++) pb[(long)o * 196608] = m[o];
}

// ---------------------------------------------------------------------------
// Stage B: fused rowdfilt + coldfilt + q2c/mag + avgpool(ll2) on ll.
// Block (16,16): Y=16*by+ty, X=16*bx+tx (0..127). Z slots 0, 7..12.
// ---------------------------------------------------------------------------
__global__ __launch_bounds__(256) void k_fusedB(
    const float* __restrict__ ll,
    const float* __restrict__ h0a, const float* __restrict__ h0b,
    const float* __restrict__ h1a, const float* __restrict__ h1b,
    float* __restrict__ Z)
{
    __shared__ float sll[80][81];  // ll rows [64by-8,64by+71], cols [64bx-8,64bx+71]
    __shared__ float sl2[80][32];  // lo2: rows same window, cols [32bx,32bx+31]
    __shared__ float sh2[80][32];

    const int bx = blockIdx.x, by = blockIdx.y, img = blockIdx.z;
    const int tx = threadIdx.x, ty = threadIdx.y;
    const int tid = ty * 16 + tx;
    const float* lim = ll + (long)img * 262144;
    const int r0 = 64 * by - 8, c0 = 64 * bx - 8;

    float fa0[10], fb0[10], fa1[10], fb1[10];
#pragma unroll
    for (int k = 0; k < 10; k++) {
        fa0[k] = __ldg(h0a + k); fb0[k] = __ldg(h0b + k);
        fa1[k] = __ldg(h1a + k); fb1[k] = __ldg(h1b + k);
    }

    for (int idx = tid; idx < 80 * 80; idx += 256) {
        int rr = idx / 80, cc = idx - rr * 80;
        sll[rr][cc] = lim[(long)refl(r0 + rr, 512) * 512 + refl(c0 + cc, 512)];
    }
    __syncthreads();

    // rowdfilt: 80 rows x 16 col-pairs. pair p -> lo2/hi2 cols 2p, 2p+1.
    // lo even col: h0b @ even set; lo odd: h0a @ odd set;
    // hi even col: h1a @ odd set; hi odd: h1b @ even set.
    for (int idx = tid; idx < 80 * 16; idx += 256) {
        int rr = idx >> 4, pp = idx & 15;
        int base = 4 * pp;
        float se = 0.f, so = 0.f, te = 0.f, to = 0.f;
#pragma unroll
        for (int k = 0; k < 10; k++) {
            float ve = sll[rr][base + 2 * k];
            float vo = sll[rr][base + 1 + 2 * k];
            se += fb0[k] * ve;
            so += fa0[k] * vo;
            te += fa1[k] * vo;
            to += fb1[k] * ve;
        }
        sl2[rr][2 * pp]     = se;
        sl2[rr][2 * pp + 1] = so;
        sh2[rr][2 * pp]     = te;
        sh2[rr][2 * pp + 1] = to;
    }
    __syncthreads();

    // coldfilt: local rows 4ty+2k (even set), +1 (odd set); local cols 2tx, 2tx+1
    float ll0x=0,ll0y=0,ll1x=0,ll1y=0, lh0x=0,lh0y=0,lh1x=0,lh1y=0;
    float hl0x=0,hl0y=0,hl1x=0,hl1y=0, hh0x=0,hh0y=0,hh1x=0,hh1y=0;
#pragma unroll
    for (int k = 0; k < 10; k++) {
        int lrE = 4 * ty + 2 * k, lrO = lrE + 1;
        float ax = sl2[lrE][2*tx], ay = sl2[lrE][2*tx+1];
        float qx = sl2[lrO][2*tx], qy = sl2[lrO][2*tx+1];
        float cx = sh2[lrE][2*tx], cy = sh2[lrE][2*tx+1];
        float dx = sh2[lrO][2*tx], dy = sh2[lrO][2*tx+1];
        float c0b = fb0[k], c0a = fa0[k], c1a = fa1[k], c1b = fb1[k];
        ll0x += c0b*ax; ll0y += c0b*ay;  ll1x += c0a*qx; ll1y += c0a*qy;
        lh0x += c1a*qx; lh0y += c1a*qy;  lh1x += c1b*ax; lh1y += c1b*ay;
        hl0x += c0b*cx; hl0y += c0b*cy;  hl1x += c0a*dx; hl1y += c0a*dy;
        hh0x += c1a*dx; hh0y += c1a*dy;  hh1x += c1b*cx; hh1y += c1b*cy;
    }

    float s0v = 0.25f * (ll0x + ll0y + ll1x + ll1y);
    float m[6];
    q2c_mags(lh0x, lh0y, lh1x, lh1y, m[0], m[5]);
    q2c_mags(hh0x, hh0y, hh1x, hh1y, m[1], m[4]);
    q2c_mags(hl0x, hl0y, hl1x, hl1y, m[2], m[3]);

    const int Y = 16 * by + ty, X = 16 * bx + tx;
    int b = img / 3, ch = img - 3 * b;
    float* zb = Z + ((long)b * 147 + ch) * 16384 + ((long)Y * 128 + X);
    zb[0] = s0v;
#pragma unroll
    for (int o = 0; o < 6; o++) zb[(long)(7 + o) * 49152] = m[o];
}

// ---------------------------------------------------------------------------
// Stage C: fused rowfilter + colfilter + q2c/mag + avgpool(ll3) on p.
// Block (32,8): Y=8*by+ty (0..127), X=32*bx+tx (0..127). img = b*18+(3*o1+ch).
// Z slots 1..6 (avg) and 13..48 (s2).
// ---------------------------------------------------------------------------
__global__ __launch_bounds__(256) void k_fusedC(
    const float* __restrict__ p,
    const float* __restrict__ h0, const float* __restrict__ h1,
    float* __restrict__ Z)
{
    __shared__ float sx [22][72];
    __shared__ float slo[22][64];
    __shared__ float shi[22][64];

    const int bx = blockIdx.x, by = blockIdx.y, img = blockIdx.z;
    const int tx = threadIdx.x, ty = threadIdx.y;
    const int tid = ty * 32 + tx;
    const int W = 256;
    const float* xim = p + (long)img * W * W;
    const int r0 = 16 * by - 3;
    const int c0 = 64 * bx - 3;

    float f0[5], f1[7];
#pragma unroll
    for (int k = 0; k < 5; k++) f0[k] = __ldg(h0 + k);
#pragma unroll
    for (int k = 0; k < 7; k++) f1[k] = __ldg(h1 + k);

    for (int idx = tid; idx < 22 * 70; idx += 256) {
        int rr = idx / 70, cc = idx - rr * 70;
        sx[rr][cc] = xim[(long)refl(r0 + rr, W) * W + refl(c0 + cc, W)];
    }
    __syncthreads();

    for (int idx = tid; idx < 22 * 64; idx += 256) {
        int rr = idx >> 6, cc = idx & 63;
        float s1 = 0.f;
#pragma unroll
        for (int k = 0; k < 7; k++) s1 += f1[k] * sx[rr][cc + k];
        float s0 = 0.f;
#pragma unroll
        for (int k = 0; k < 5; k++) s0 += f0[k] * sx[rr][cc + 1 + k];
        slo[rr][cc] = s0;
        shi[rr][cc] = s1;
    }
    __syncthreads();

    float vll0x=0,vll0y=0,vll1x=0,vll1y=0, vlh0x=0,vlh0y=0,vlh1x=0,vlh1y=0;
    float vhl0x=0,vhl0y=0,vhl1x=0,vhl1y=0, vhh0x=0,vhh0y=0,vhh1x=0,vhh1y=0;
#pragma unroll
    for (int r = 0; r < 8; r++) {
        int lr = 2 * ty + r;
        float lx = slo[lr][2*tx], ly = slo[lr][2*tx+1];
        float hx = shi[lr][2*tx], hy = shi[lr][2*tx+1];
        if (r <= 6) { float c = f1[r];
            vlh0x += c*lx; vlh0y += c*ly; vhh0x += c*hx; vhh0y += c*hy; }
        if (r >= 1) { float c = f1[r-1];
            vlh1x += c*lx; vlh1y += c*ly; vhh1x += c*hx; vhh1y += c*hy; }
        if (r >= 1 && r <= 5) { float c = f0[r-1];
            vll0x += c*lx; vll0y += c*ly; vhl0x += c*hx; vhl0y += c*hy; }
        if (r >= 2 && r <= 6) { float c = f0[r-2];
            vll1x += c*lx; vll1y += c*ly; vhl1x += c*hx; vhl1y += c*hy; }
    }

    float avg = 0.25f * (vll0x + vll0y + vll1x + vll1y);
    float m[6];
    q2c_mags(vlh0x, vlh0y, vlh1x, vlh1y, m[0], m[5]);
    q2c_mags(vhh0x, vhh0y, vhh1x, vhh1y, m[1], m[4]);
    q2c_mags(vhl0x, vhl0y, vhl1x, vhl1y, m[2], m[3]);

    const int Y = 8 * by + ty, X = 32 * bx + tx;
    int b = img / 18;
    int c18 = img - 18 * b;
    int o1 = c18 / 3;
    int ch = c18 - 3 * o1;
    float* zb = Z + ((long)b * 147 + ch) * 16384 + ((long)Y * 128 + X);
    zb[(long)(1 + o1) * 49152] = avg;
#pragma unroll
    for (int o2 = 0; o2 < 6; o2++)
        zb[(long)(13 + o2 * 6 + o1) * 49152] = m[o2];
}

// ---------------------------------------------------------------------------
// Host launcher (graph-capturable)
// ---------------------------------------------------------------------------
extern "C" void kernel_launch(void* const* d_in, const int* in_sizes, int n_in,
                              void* d_out, int out_size)
{
    const float* x   = (const float*)d_in[0];
    const float* h0o = (const float*)d_in[1];
    const float* h1o = (const float*)d_in[2];
    const float* h0a = (const float*)d_in[3];
    const float* h0b = (const float*)d_in[4];
    const float* h1a = (const float*)d_in[5];
    const float* h1b = (const float*)d_in[6];
    float* Z = (float*)d_out;

    float *ll, *p;
    cudaGetSymbolAddress((void**)&ll, g_ll);
    cudaGetSymbolAddress((void**)&p,  g_p);

    k_fusedA<<<dim3(8, 32, 96),  dim3(32, 8)>>>(x, h0o, h1o, ll, p);
    k_fusedB<<<dim3(8, 8, 96),   dim3(16, 16)>>>(ll, h0a, h0b, h1a, h1b, Z);
    k_fusedC<<<dim3(4, 16, 576), dim3(32, 8)>>>(p, h0o, h1o, Z);
}

// round 6
// speedup vs baseline: 1.6652x; 1.1963x over previous
#include <cuda_runtime.h>

// ---------------------------------------------------------------------------
// ScatLayerj2: 2-level DTCWT scattering, fused + vectorized smem dataflow.
// x (32,3,512,512) f32 -> Z (32,147,128,128) f32
// ---------------------------------------------------------------------------

static __device__ __forceinline__ int refl(int p, int l) {
    if (p < 0)  p = -1 - p;
    if (p >= l) p = 2 * l - 1 - p;
    return p;
}

static __device__ __forceinline__ float smag(float re, float im) {
    return sqrtf(re * re + im * im + 1e-4f) - 0.01f;
}

static __device__ __forceinline__ void q2c_mags(float v0x, float v0y, float v1x, float v1y,
                                                float& m_first, float& m_second) {
    const float s = 0.70710678118654752440f;
    float a = v0x * s, b = v0y * s, c = v1x * s, d = v1y * s;
    m_first  = smag(a - d, b + c);
    m_second = smag(a + d, b - c);
}

// Scratch: ll (96*512*512) and p (576*256*256)
__device__ float g_ll[25165824];
__device__ float g_p [37748736];

// ---------------------------------------------------------------------------
// j1 fused core: rowfilter(h0:5,h1:7) + colfilter into 8 float4 accumulators.
// Block (32,8). Out tile: 8 rows x 64 cols (pairs). lo/hi tile: 22 x 128.
// sx local col 0 <-> global col c0 = 128*bx - 4.
// lo local col cc <-> global col 128*bx + cc.
//   h0 taps: sx[rr][cc+2+k], k=0..4 ; h1 taps: sx[rr][cc+1+k], k=0..6
// ---------------------------------------------------------------------------
struct J1Out {
    float4 ll0, ll1;   // ll rows 2Y, 2Y+1, cols 4tx..4tx+3
    float  m[2][6];    // per pair (2tx, 2tx+1): 6 orientation magnitudes
};

template<int W>
static __device__ __forceinline__ void j1_core(
    const float* __restrict__ xim,
    const float* __restrict__ h0, const float* __restrict__ h1,
    int bx, int by, J1Out& out)
{
    __shared__ float sx [22][136];   // rows [16by-3,16by+18], cols [128bx-4,128bx+131]
    __shared__ float slo[22][128];
    __shared__ float shi[22][128];

    const int tx = threadIdx.x, ty = threadIdx.y;
    const int tid = ty * 32 + tx;
    const int r0 = 16 * by - 3;
    const int c0 = 128 * bx - 4;

    float f0[5], f1[7];
#pragma unroll
    for (int k = 0; k < 5; k++) f0[k] = __ldg(h0 + k);
#pragma unroll
    for (int k = 0; k < 7; k++) f1[k] = __ldg(h1 + k);

    // ---- global load: 22 rows x 34 float4 ----
    for (int idx = tid; idx < 22 * 34; idx += 256) {
        int rr = idx / 34, q = idx - rr * 34;
        int c = c0 + 4 * q;
        const float* rowp = xim + (long)refl(r0 + rr, W) * W;
        float4* dst = (float4*)sx[rr];
        if (c >= 0 && c + 3 < W) {
            dst[q] = *(const float4*)(rowp + c);
        } else {
            float t0 = rowp[refl(c, W)];
            float t1 = rowp[refl(c + 1, W)];
            float t2 = rowp[refl(c + 2, W)];
            float t3 = rowp[refl(c + 3, W)];
            dst[q] = make_float4(t0, t1, t2, t3);
        }
    }
    __syncthreads();

    // ---- row filter: 22 rows x 32 quad-tasks (4 outputs each) ----
    for (int idx = tid; idx < 22 * 32; idx += 256) {
        int rr = idx >> 5, q = idx & 31;
        const float4* rowv = (const float4*)sx[rr];
        float4 A = rowv[q], B = rowv[q + 1], C = rowv[q + 2];
        float v[12] = {A.x, A.y, A.z, A.w, B.x, B.y, B.z, B.w, C.x, C.y, C.z, C.w};
        float o0[4], o1[4];
#pragma unroll
        for (int j = 0; j < 4; j++) {
            float s1 = 0.f;
#pragma unroll
            for (int k = 0; k < 7; k++) s1 += f1[k] * v[j + 1 + k];
            float s0 = 0.f;
#pragma unroll
            for (int k = 0; k < 5; k++) s0 += f0[k] * v[j + 2 + k];
            o0[j] = s0; o1[j] = s1;
        }
        ((float4*)slo[rr])[q] = make_float4(o0[0], o0[1], o0[2], o0[3]);
        ((float4*)shi[rr])[q] = make_float4(o1[0], o1[1], o1[2], o1[3]);
    }
    __syncthreads();

    // ---- col filter: thread handles pairs {2tx, 2tx+1} = lo cols 4tx..4tx+3,
    //      out row ty (lo rows 2ty..2ty+7) ----
    float4 all0 = {0,0,0,0}, all1 = {0,0,0,0}, alh0 = {0,0,0,0}, alh1 = {0,0,0,0};
    float4 ahl0 = {0,0,0,0}, ahl1 = {0,0,0,0}, ahh0 = {0,0,0,0}, ahh1 = {0,0,0,0};
#pragma unroll
    for (int r = 0; r < 8; r++) {
        int lr = 2 * ty + r;
        float4 l = ((const float4*)slo[lr])[tx];
        float4 h = ((const float4*)shi[lr])[tx];
        if (r <= 6) { float c = f1[r];
            alh0.x += c*l.x; alh0.y += c*l.y; alh0.z += c*l.z; alh0.w += c*l.w;
            ahh0.x += c*h.x; ahh0.y += c*h.y; ahh0.z += c*h.z; ahh0.w += c*h.w; }
        if (r >= 1) { float c = f1[r-1];
            alh1.x += c*l.x; alh1.y += c*l.y; alh1.z += c*l.z; alh1.w += c*l.w;
            ahh1.x += c*h.x; ahh1.y += c*h.y; ahh1.z += c*h.z; ahh1.w += c*h.w; }
        if (r >= 1 && r <= 5) { float c = f0[r-1];
            all0.x += c*l.x; all0.y += c*l.y; all0.z += c*l.z; all0.w += c*l.w;
            ahl0.x += c*h.x; ahl0.y += c*h.y; ahl0.z += c*h.z; ahl0.w += c*h.w; }
        if (r >= 2 && r <= 6) { float c = f0[r-2];
            all1.x += c*l.x; all1.y += c*l.y; all1.z += c*l.z; all1.w += c*l.w;
            ahl1.x += c*h.x; ahl1.y += c*h.y; ahl1.z += c*h.z; ahl1.w += c*h.w; }
    }

    out.ll0 = all0; out.ll1 = all1;
    // pair 0 = (.x,.y), pair 1 = (.z,.w)
    q2c_mags(alh0.x, alh0.y, alh1.x, alh1.y, out.m[0][0], out.m[0][5]);
    q2c_mags(ahh0.x, ahh0.y, ahh1.x, ahh1.y, out.m[0][1], out.m[0][4]);
    q2c_mags(ahl0.x, ahl0.y, ahl1.x, ahl1.y, out.m[0][2], out.m[0][3]);
    q2c_mags(alh0.z, alh0.w, alh1.z, alh1.w, out.m[1][0], out.m[1][5]);
    q2c_mags(ahh0.z, ahh0.w, ahh1.z, ahh1.w, out.m[1][1], out.m[1][4]);
    q2c_mags(ahl0.z, ahl0.w, ahl1.z, ahl1.w, out.m[1][2], out.m[1][3]);
}

// ---------------------------------------------------------------------------
// Stage A: j1 on x (96 imgs, W=512). Writes ll (96,512,512), p (32,18,256,256).
// Grid (4, 32, 96), block (32,8).
// ---------------------------------------------------------------------------
__global__ __launch_bounds__(256) void k_fusedA(
    const float* __restrict__ x,
    const float* __restrict__ h0, const float* __restrict__ h1,
    float* __restrict__ ll, float* __restrict__ p)
{
    const int bx = blockIdx.x, by = blockIdx.y, img = blockIdx.z;
    const int tx = threadIdx.x, ty = threadIdx.y;
    J1Out o;
    j1_core<512>(x + (long)img * 262144, h0, h1, bx, by, o);

    const int Y = 8 * by + ty;
    const int llc = 128 * bx + 4 * tx;
    float* llp = ll + (long)img * 262144;
    *(float4*)(llp + (long)(2 * Y) * 512 + llc)     = o.ll0;
    *(float4*)(llp + (long)(2 * Y + 1) * 512 + llc) = o.ll1;

    int b = img / 3, ch = img - 3 * b;
    const int X = 64 * bx + 2 * tx;
    float* pb = p + ((long)b * 18 + ch) * 65536 + ((long)Y * 256 + X);
#pragma unroll
    for (int oo = 0; oo < 6; oo++)
        *(float2*)(pb + (long)oo * 196608) = make_float2(o.m[0][oo], o.m[1][oo]);
}

// ---------------------------------------------------------------------------
// Stage C: j1 on p (576 imgs, W=256). Writes Z slots 1..6, 13..48.
// Grid (2, 16, 576), block (32,8).
// ---------------------------------------------------------------------------
__global__ __launch_bounds__(256) void k_fusedC(
    const float* __restrict__ p,
    const float* __restrict__ h0, const float* __restrict__ h1,
    float* __restrict__ Z)
{
    const int bx = blockIdx.x, by = blockIdx.y, img = blockIdx.z;
    const int tx = threadIdx.x, ty = threadIdx.y;
    J1Out o;
    j1_core<256>(p + (long)img * 65536, h0, h1, bx, by, o);

    const int Y = 8 * by + ty;
    const int X = 64 * bx + 2 * tx;
    int b = img / 18;
    int c18 = img - 18 * b;
    int o1 = c18 / 3;
    int ch = c18 - 3 * o1;

    float avg0 = 0.25f * (o.ll0.x + o.ll0.y + o.ll1.x + o.ll1.y);
    float avg1 = 0.25f * (o.ll0.z + o.ll0.w + o.ll1.z + o.ll1.w);

    float* zb = Z + ((long)b * 147 + ch) * 16384 + ((long)Y * 128 + X);
    *(float2*)(zb + (long)(1 + o1) * 49152) = make_float2(avg0, avg1);
#pragma unroll
    for (int o2 = 0; o2 < 6; o2++)
        *(float2*)(zb + (long)(13 + o2 * 6 + o1) * 49152) = make_float2(o.m[0][o2], o.m[1][o2]);
}

// ---------------------------------------------------------------------------
// Stage B: fused rowdfilt + coldfilt + q2c/mag + avgpool(ll2) on ll.
// Block (16,16): Y=16*by+ty, X=16*bx+tx (0..127). Z slots 0, 7..12.
// ---------------------------------------------------------------------------
__global__ __launch_bounds__(256) void k_fusedB(
    const float* __restrict__ ll,
    const float* __restrict__ h0a, const float* __restrict__ h0b,
    const float* __restrict__ h1a, const float* __restrict__ h1b,
    float* __restrict__ Z)
{
    __shared__ float sll[80][84];  // ll rows/cols [64b-8, 64b+71]
    __shared__ float sl2[80][32];
    __shared__ float sh2[80][32];

    const int bx = blockIdx.x, by = blockIdx.y, img = blockIdx.z;
    const int tx = threadIdx.x, ty = threadIdx.y;
    const int tid = ty * 16 + tx;
    const float* lim = ll + (long)img * 262144;
    const int r0 = 64 * by - 8, c0 = 64 * bx - 8;

    float fa0[10], fb0[10], fa1[10], fb1[10];
#pragma unroll
    for (int k = 0; k < 10; k++) {
        fa0[k] = __ldg(h0a + k); fb0[k] = __ldg(h0b + k);
        fa1[k] = __ldg(h1a + k); fb1[k] = __ldg(h1b + k);
    }

    // ---- load: 80 rows x 20 float4 ----
    for (int idx = tid; idx < 80 * 20; idx += 256) {
        int rr = idx / 20, q = idx - rr * 20;
        int c = c0 + 4 * q;
        const float* rowp = lim + (long)refl(r0 + rr, 512) * 512;
        float4* dst = (float4*)sll[rr];
        if (c >= 0 && c + 3 < 512) {
            dst[q] = *(const float4*)(rowp + c);
        } else {
            float t0 = rowp[refl(c, 512)];
            float t1 = rowp[refl(c + 1, 512)];
            float t2 = rowp[refl(c + 2, 512)];
            float t3 = rowp[refl(c + 3, 512)];
            dst[q] = make_float4(t0, t1, t2, t3);
        }
    }
    __syncthreads();

    // ---- rowdfilt: 80 rows x 8 quad-tasks (4 out cols each) ----
    // out col even (2p):   lo <- h0b over even set, hi <- h1b -> odd out? see mapping:
    //   lo even: h0b @ sll[4p+2k];  lo odd: h0a @ sll[4p+1+2k]
    //   hi even: h1a @ sll[4p+1+2k]; hi odd: h1b @ sll[4p+2k]
    for (int idx = tid; idx < 80 * 8; idx += 256) {
        int rr = idx >> 3, qq = idx & 7;
        const float4* rowv = (const float4*)sll[rr];
        float w[24];
#pragma unroll
        for (int j = 0; j < 6; j++) {
            float4 v = rowv[2 * qq + j];
            w[4*j] = v.x; w[4*j+1] = v.y; w[4*j+2] = v.z; w[4*j+3] = v.w;
        }
        float lo_o[4], hi_o[4];
#pragma unroll
        for (int j = 0; j < 2; j++) {
            float se = 0.f, so = 0.f, te = 0.f, to = 0.f;
#pragma unroll
            for (int k = 0; k < 10; k++) {
                float ve = w[4 * j + 2 * k];
                float vo = w[4 * j + 1 + 2 * k];
                se += fb0[k] * ve;
                so += fa0[k] * vo;
                te += fa1[k] * vo;
                to += fb1[k] * ve;
            }
            lo_o[2*j] = se; lo_o[2*j+1] = so;
            hi_o[2*j] = te; hi_o[2*j+1] = to;
        }
        ((float4*)sl2[rr])[qq] = make_float4(lo_o[0], lo_o[1], lo_o[2], lo_o[3]);
        ((float4*)sh2[rr])[qq] = make_float4(hi_o[0], hi_o[1], hi_o[2], hi_o[3]);
    }
    __syncthreads();

    // ---- coldfilt + q2c + avgpool ----
    float ll0x=0,ll0y=0,ll1x=0,ll1y=0, lh0x=0,lh0y=0,lh1x=0,lh1y=0;
    float hl0x=0,hl0y=0,hl1x=0,hl1y=0, hh0x=0,hh0y=0,hh1x=0,hh1y=0;
#pragma unroll
    for (int k = 0; k < 10; k++) {
        int lrE = 4 * ty + 2 * k, lrO = lrE + 1;
        float2 a = ((const float2*)sl2[lrE])[tx];
        float2 q = ((const float2*)sl2[lrO])[tx];
        float2 c = ((const float2*)sh2[lrE])[tx];
        float2 d = ((const float2*)sh2[lrO])[tx];
        float c0b = fb0[k], c0a = fa0[k], c1a = fa1[k], c1b = fb1[k];
        ll0x += c0b*a.x; ll0y += c0b*a.y;  ll1x += c0a*q.x; ll1y += c0a*q.y;
        lh0x += c1a*q.x; lh0y += c1a*q.y;  lh1x += c1b*a.x; lh1y += c1b*a.y;
        hl0x += c0b*c.x; hl0y += c0b*c.y;  hl1x += c0a*d.x; hl1y += c0a*d.y;
        hh0x += c1a*d.x; hh0y += c1a*d.y;  hh1x += c1b*c.x; hh1y += c1b*c.y;
    }

    float s0v = 0.25f * (ll0x + ll0y + ll1x + ll1y);
    float m[6];
    q2c_mags(lh0x, lh0y, lh1x, lh1y, m[0], m[5]);
    q2c_mags(hh0x, hh0y, hh1x, hh1y, m[1], m[4]);
    q2c_mags(hl0x, hl0y, hl1x, hl1y, m[2], m[3]);

    const int Y = 16 * by + ty, X = 16 * bx + tx;
    int b = img / 3, ch = img - 3 * b;
    float* zb = Z + ((long)b * 147 + ch) * 16384 + ((long)Y * 128 + X);
    zb[0] = s0v;
#pragma unroll
    for (int o = 0; o < 6; o++) zb[(long)(7 + o) * 49152] = m[o];
}

// ---------------------------------------------------------------------------
// Host launcher (graph-capturable)
// ---------------------------------------------------------------------------
extern "C" void kernel_launch(void* const* d_in, const int* in_sizes, int n_in,
                              void* d_out, int out_size)
{
    const float* x   = (const float*)d_in[0];
    const float* h0o = (const float*)d_in[1];
    const float* h1o = (const float*)d_in[2];
    const float* h0a = (const float*)d_in[3];
    const float* h0b = (const float*)d_in[4];
    const float* h1a = (const float*)d_in[5];
    const float* h1b = (const float*)d_in[6];
    float* Z = (float*)d_out;

    float *ll, *p;
    cudaGetSymbolAddress((void**)&ll, g_ll);
    cudaGetSymbolAddress((void**)&p,  g_p);

    k_fusedA<<<dim3(4, 32, 96),  dim3(32, 8)>>>(x, h0o, h1o, ll, p);
    k_fusedB<<<dim3(8, 8, 96),   dim3(16, 16)>>>(ll, h0a, h0b, h1a, h1b, Z);
    k_fusedC<<<dim3(2, 16, 576), dim3(32, 8)>>>(p, h0o, h1o, Z);
}

// round 7
// speedup vs baseline: 2.0964x; 1.2590x over previous
#include <cuda_runtime.h>

// ---------------------------------------------------------------------------
// ScatLayerj2: 2-level DTCWT scattering, fused, vectorized, occupancy-tuned.
// x (32,3,512,512) f32 -> Z (32,147,128,128) f32
// ---------------------------------------------------------------------------

static __device__ __forceinline__ int refl(int p, int l) {
    if (p < 0)  p = -1 - p;
    if (p >= l) p = 2 * l - 1 - p;
    return p;
}

static __device__ __forceinline__ float smag(float re, float im) {
    return sqrtf(re * re + im * im + 1e-4f) - 0.01f;
}

static __device__ __forceinline__ void q2c_mags(float v0x, float v0y, float v1x, float v1y,
                                                float& m_first, float& m_second) {
    const float s = 0.70710678118654752440f;
    float a = v0x * s, b = v0y * s, c = v1x * s, d = v1y * s;
    m_first  = smag(a - d, b + c);
    m_second = smag(a + d, b - c);
}

// Scratch: ll (96*512*512) and p (576*256*256)
__device__ float g_ll[25165824];
__device__ float g_p [37748736];

// ---------------------------------------------------------------------------
// j1 fused core: (global load + rowfilter) -> smem lo/hi -> split col filter.
// Block (32,8). Out tile: 8 rows x 64 pairs (128 px wide). lo/hi tile 22x128.
// lo local col cc <-> global col 128*bx + cc; window = global cols
// [128bx+cc-3, 128bx+cc+3] for h1, [.. -2, ..+2]+? (h0 at +1 offset in window).
// ---------------------------------------------------------------------------
struct J1Out {
    float4 ll0, ll1;   // ll rows 2Y,2Y+1, cols 4tx..4tx+3
    float  m[2][6];    // per pair (2tx,2tx+1): 6 orientation magnitudes
};

template<int W>
static __device__ __forceinline__ void j1_core(
    const float* __restrict__ xim,
    const float* __restrict__ h0, const float* __restrict__ h1,
    int bx, int by, J1Out& out)
{
    __shared__ float slo[22][128];
    __shared__ float shi[22][128];

    const int tx = threadIdx.x, ty = threadIdx.y;
    const int tid = ty * 32 + tx;
    const int r0 = 16 * by - 3;
    const int c0 = 128 * bx - 4;

    float f0[5], f1[7];
#pragma unroll
    for (int k = 0; k < 5; k++) f0[k] = __ldg(h0 + k);
#pragma unroll
    for (int k = 0; k < 7; k++) f1[k] = __ldg(h1 + k);

    // ---- phase 1: fused global load + row filter. 22 rows x 32 quad-tasks ----
    for (int idx = tid; idx < 22 * 32; idx += 256) {
        int rr = idx >> 5, q = idx & 31;
        int c = c0 + 4 * q;   // window = x cols c .. c+11; outputs use c+1..c+10
        const float* rowp = xim + (long)refl(r0 + rr, W) * W;
        float w[12];
        if (c >= 0 && c + 11 < W) {
            float4 A = *(const float4*)(rowp + c);
            float4 Bv = *(const float4*)(rowp + c + 4);
            float4 Cv = *(const float4*)(rowp + c + 8);
            w[0]=A.x; w[1]=A.y; w[2]=A.z; w[3]=A.w;
            w[4]=Bv.x; w[5]=Bv.y; w[6]=Bv.z; w[7]=Bv.w;
            w[8]=Cv.x; w[9]=Cv.y; w[10]=Cv.z; w[11]=Cv.w;
        } else {
#pragma unroll
            for (int j = 0; j < 12; j++) w[j] = rowp[refl(c + j, W)];
        }
        float o0[4], o1[4];
#pragma unroll
        for (int j = 0; j < 4; j++) {
            float s1 = 0.f;
#pragma unroll
            for (int k = 0; k < 7; k++) s1 += f1[k] * w[j + 1 + k];
            float s0 = 0.f;
#pragma unroll
            for (int k = 0; k < 5; k++) s0 += f0[k] * w[j + 2 + k];
            o0[j] = s0; o1[j] = s1;
        }
        ((float4*)slo[rr])[q] = make_float4(o0[0], o0[1], o0[2], o0[3]);
        ((float4*)shi[rr])[q] = make_float4(o1[0], o1[1], o1[2], o1[3]);
    }
    __syncthreads();

    // ---- phase 2a: lo branch (ll, lh) ----
    {
        float4 all0 = {0,0,0,0}, all1 = {0,0,0,0}, alh0 = {0,0,0,0}, alh1 = {0,0,0,0};
#pragma unroll
        for (int r = 0; r < 8; r++) {
            float4 l = ((const float4*)slo[2 * ty + r])[tx];
            if (r <= 6) { float c = f1[r];
                alh0.x += c*l.x; alh0.y += c*l.y; alh0.z += c*l.z; alh0.w += c*l.w; }
            if (r >= 1) { float c = f1[r-1];
                alh1.x += c*l.x; alh1.y += c*l.y; alh1.z += c*l.z; alh1.w += c*l.w; }
            if (r >= 1 && r <= 5) { float c = f0[r-1];
                all0.x += c*l.x; all0.y += c*l.y; all0.z += c*l.z; all0.w += c*l.w; }
            if (r >= 2 && r <= 6) { float c = f0[r-2];
                all1.x += c*l.x; all1.y += c*l.y; all1.z += c*l.z; all1.w += c*l.w; }
        }
        out.ll0 = all0; out.ll1 = all1;
        q2c_mags(alh0.x, alh0.y, alh1.x, alh1.y, out.m[0][0], out.m[0][5]);
        q2c_mags(alh0.z, alh0.w, alh1.z, alh1.w, out.m[1][0], out.m[1][5]);
    }
    // ---- phase 2b: hi branch (hl, hh) ----
    {
        float4 ahl0 = {0,0,0,0}, ahl1 = {0,0,0,0}, ahh0 = {0,0,0,0}, ahh1 = {0,0,0,0};
#pragma unroll
        for (int r = 0; r < 8; r++) {
            float4 h = ((const float4*)shi[2 * ty + r])[tx];
            if (r <= 6) { float c = f1[r];
                ahh0.x += c*h.x; ahh0.y += c*h.y; ahh0.z += c*h.z; ahh0.w += c*h.w; }
            if (r >= 1) { float c = f1[r-1];
                ahh1.x += c*h.x; ahh1.y += c*h.y; ahh1.z += c*h.z; ahh1.w += c*h.w; }
            if (r >= 1 && r <= 5) { float c = f0[r-1];
                ahl0.x += c*h.x; ahl0.y += c*h.y; ahl0.z += c*h.z; ahl0.w += c*h.w; }
            if (r >= 2 && r <= 6) { float c = f0[r-2];
                ahl1.x += c*h.x; ahl1.y += c*h.y; ahl1.z += c*h.z; ahl1.w += c*h.w; }
        }
        q2c_mags(ahh0.x, ahh0.y, ahh1.x, ahh1.y, out.m[0][1], out.m[0][4]);
        q2c_mags(ahh0.z, ahh0.w, ahh1.z, ahh1.w, out.m[1][1], out.m[1][4]);
        q2c_mags(ahl0.x, ahl0.y, ahl1.x, ahl1.y, out.m[0][2], out.m[0][3]);
        q2c_mags(ahl0.z, ahl0.w, ahl1.z, ahl1.w, out.m[1][2], out.m[1][3]);
    }
}

// ---------------------------------------------------------------------------
// Stage A: j1 on x (96 imgs, W=512). Grid (4,32,96), block (32,8).
// ---------------------------------------------------------------------------
__global__ __launch_bounds__(256, 4) void k_fusedA(
    const float* __restrict__ x,
    const float* __restrict__ h0, const float* __restrict__ h1,
    float* __restrict__ ll, float* __restrict__ p)
{
    const int bx = blockIdx.x, by = blockIdx.y, img = blockIdx.z;
    const int tx = threadIdx.x, ty = threadIdx.y;
    J1Out o;
    j1_core<512>(x + (long)img * 262144, h0, h1, bx, by, o);

    const int Y = 8 * by + ty;
    const int llc = 128 * bx + 4 * tx;
    float* llp = ll + (long)img * 262144;
    *(float4*)(llp + (long)(2 * Y) * 512 + llc)     = o.ll0;
    *(float4*)(llp + (long)(2 * Y + 1) * 512 + llc) = o.ll1;

    int b = img / 3, ch = img - 3 * b;
    const int X = 64 * bx + 2 * tx;
    float* pb = p + ((long)b * 18 + ch) * 65536 + ((long)Y * 256 + X);
#pragma unroll
    for (int oo = 0; oo < 6; oo++)
        *(float2*)(pb + (long)oo * 196608) = make_float2(o.m[0][oo], o.m[1][oo]);
}

// ---------------------------------------------------------------------------
// Stage C: j1 on p (576 imgs, W=256). Grid (2,16,576), block (32,8).
// ---------------------------------------------------------------------------
__global__ __launch_bounds__(256, 4) void k_fusedC(
    const float* __restrict__ p,
    const float* __restrict__ h0, const float* __restrict__ h1,
    float* __restrict__ Z)
{
    const int bx = blockIdx.x, by = blockIdx.y, img = blockIdx.z;
    const int tx = threadIdx.x, ty = threadIdx.y;
    J1Out o;
    j1_core<256>(p + (long)img * 65536, h0, h1, bx, by, o);

    const int Y = 8 * by + ty;
    const int X = 64 * bx + 2 * tx;
    int b = img / 18;
    int c18 = img - 18 * b;
    int o1 = c18 / 3;
    int ch = c18 - 3 * o1;

    float avg0 = 0.25f * (o.ll0.x + o.ll0.y + o.ll1.x + o.ll1.y);
    float avg1 = 0.25f * (o.ll0.z + o.ll0.w + o.ll1.z + o.ll1.w);

    float* zb = Z + ((long)b * 147 + ch) * 16384 + ((long)Y * 128 + X);
    *(float2*)(zb + (long)(1 + o1) * 49152) = make_float2(avg0, avg1);
#pragma unroll
    for (int o2 = 0; o2 < 6; o2++)
        *(float2*)(zb + (long)(13 + o2 * 6 + o1) * 49152) = make_float2(o.m[0][o2], o.m[1][o2]);
}

// ---------------------------------------------------------------------------
// Stage B: fused (global load + rowdfilt) -> smem -> split coldfilt + q2c +
// avgpool. Block (16,16): Y=16*by+ty, X=16*bx+tx. Z slots 0, 7..12.
// ---------------------------------------------------------------------------
__global__ __launch_bounds__(256, 4) void k_fusedB(
    const float* __restrict__ ll,
    const float* __restrict__ h0a, const float* __restrict__ h0b,
    const float* __restrict__ h1a, const float* __restrict__ h1b,
    float* __restrict__ Z)
{
    __shared__ float sl2[80][32];
    __shared__ float sh2[80][32];

    const int bx = blockIdx.x, by = blockIdx.y, img = blockIdx.z;
    const int tx = threadIdx.x, ty = threadIdx.y;
    const int tid = ty * 16 + tx;
    const float* lim = ll + (long)img * 262144;
    const int r0 = 64 * by - 8, c0 = 64 * bx - 8;

    float fa0[10], fb0[10], fa1[10], fb1[10];
#pragma unroll
    for (int k = 0; k < 10; k++) {
        fa0[k] = __ldg(h0a + k); fb0[k] = __ldg(h0b + k);
        fa1[k] = __ldg(h1a + k); fb1[k] = __ldg(h1b + k);
    }

    // ---- phase 1: fused load + rowdfilt. 80 rows x 8 quad-tasks ----
    // out cols 4qq..4qq+3 from ll window cols c..c+23, c = c0 + 8*qq.
    //   lo even: h0b @ w[2k];  lo odd: h0a @ w[1+2k]
    //   hi even: h1a @ w[1+2k]; hi odd: h1b @ w[2k]   (within 4-col group: +4j)
    for (int idx = tid; idx < 80 * 8; idx += 256) {
        int rr = idx >> 3, qq = idx & 7;
        int c = c0 + 8 * qq;
        const float* rowp = lim + (long)refl(r0 + rr, 512) * 512;
        float w[24];
        if (c >= 0 && c + 23 < 512) {
#pragma unroll
            for (int j = 0; j < 6; j++) {
                float4 v = *(const float4*)(rowp + c + 4 * j);
                w[4*j] = v.x; w[4*j+1] = v.y; w[4*j+2] = v.z; w[4*j+3] = v.w;
            }
        } else {
#pragma unroll
            for (int j = 0; j < 24; j++) w[j] = rowp[refl(c + j, 512)];
        }
        float lo_o[4], hi_o[4];
#pragma unroll
        for (int j = 0; j < 2; j++) {
            float se = 0.f, so = 0.f, te = 0.f, to = 0.f;
#pragma unroll
            for (int k = 0; k < 10; k++) {
                float ve = w[4 * j + 2 * k];
                float vo = w[4 * j + 1 + 2 * k];
                se += fb0[k] * ve;
                so += fa0[k] * vo;
                te += fa1[k] * vo;
                to += fb1[k] * ve;
            }
            lo_o[2*j] = se; lo_o[2*j+1] = so;
            hi_o[2*j] = te; hi_o[2*j+1] = to;
        }
        ((float4*)sl2[rr])[qq] = make_float4(lo_o[0], lo_o[1], lo_o[2], lo_o[3]);
        ((float4*)sh2[rr])[qq] = make_float4(hi_o[0], hi_o[1], hi_o[2], hi_o[3]);
    }
    __syncthreads();

    // ---- phase 2a: lo branch (ll2, lh2) ----
    float s0v;
    float m[6];
    {
        float ll0x=0,ll0y=0,ll1x=0,ll1y=0, lh0x=0,lh0y=0,lh1x=0,lh1y=0;
#pragma unroll
        for (int k = 0; k < 10; k++) {
            int lrE = 4 * ty + 2 * k, lrO = lrE + 1;
            float2 a = ((const float2*)sl2[lrE])[tx];
            float2 q = ((const float2*)sl2[lrO])[tx];
            float c0b = fb0[k], c0a = fa0[k], c1a = fa1[k], c1b = fb1[k];
            ll0x += c0b*a.x; ll0y += c0b*a.y;  ll1x += c0a*q.x; ll1y += c0a*q.y;
            lh0x += c1a*q.x; lh0y += c1a*q.y;  lh1x += c1b*a.x; lh1y += c1b*a.y;
        }
        s0v = 0.25f * (ll0x + ll0y + ll1x + ll1y);
        q2c_mags(lh0x, lh0y, lh1x, lh1y, m[0], m[5]);
    }
    // ---- phase 2b: hi branch (hl2, hh2) ----
    {
        float hl0x=0,hl0y=0,hl1x=0,hl1y=0, hh0x=0,hh0y=0,hh1x=0,hh1y=0;
#pragma unroll
        for (int k = 0; k < 10; k++) {
            int lrE = 4 * ty + 2 * k, lrO = lrE + 1;
            float2 c = ((const float2*)sh2[lrE])[tx];
            float2 d = ((const float2*)sh2[lrO])[tx];
            float c0b = fb0[k], c0a = fa0[k], c1a = fa1[k], c1b = fb1[k];
            hl0x += c0b*c.x; hl0y += c0b*c.y;  hl1x += c0a*d.x; hl1y += c0a*d.y;
            hh0x += c1a*d.x; hh0y += c1a*d.y;  hh1x += c1b*c.x; hh1y += c1b*c.y;
        }
        q2c_mags(hh0x, hh0y, hh1x, hh1y, m[1], m[4]);
        q2c_mags(hl0x, hl0y, hl1x, hl1y, m[2], m[3]);
    }

    const int Y = 16 * by + ty, X = 16 * bx + tx;
    int b = img / 3, ch = img - 3 * b;
    float* zb = Z + ((long)b * 147 + ch) * 16384 + ((long)Y * 128 + X);
    zb[0] = s0v;
#pragma unroll
    for (int o = 0; o < 6; o++) zb[(long)(7 + o) * 49152] = m[o];
}

// ---------------------------------------------------------------------------
// Host launcher (graph-capturable)
// ---------------------------------------------------------------------------
extern "C" void kernel_launch(void* const* d_in, const int* in_sizes, int n_in,
                              void* d_out, int out_size)
{
    const float* x   = (const float*)d_in[0];
    const float* h0o = (const float*)d_in[1];
    const float* h1o = (const float*)d_in[2];
    const float* h0a = (const float*)d_in[3];
    const float* h0b = (const float*)d_in[4];
    const float* h1a = (const float*)d_in[5];
    const float* h1b = (const float*)d_in[6];
    float* Z = (float*)d_out;

    float *ll, *p;
    cudaGetSymbolAddress((void**)&ll, g_ll);
    cudaGetSymbolAddress((void**)&p,  g_p);

    k_fusedA<<<dim3(4, 32, 96),  dim3(32, 8)>>>(x, h0o, h1o, ll, p);
    k_fusedB<<<dim3(8, 8, 96),   dim3(16, 16)>>>(ll, h0a, h0b, h1a, h1b, Z);
    k_fusedC<<<dim3(2, 16, 576), dim3(32, 8)>>>(p, h0o, h1o, Z);
}

// round 8
// speedup vs baseline: 2.4724x; 1.1794x over previous
#include <cuda_runtime.h>

// ---------------------------------------------------------------------------
// ScatLayerj2: 2-level DTCWT scattering. Fused, vectorized, 2 rows/thread.
// x (32,3,512,512) f32 -> Z (32,147,128,128) f32
// ---------------------------------------------------------------------------

static __device__ __forceinline__ int refl(int p, int l) {
    if (p < 0)  p = -1 - p;
    if (p >= l) p = 2 * l - 1 - p;
    return p;
}

static __device__ __forceinline__ float smag(float re, float im) {
    return sqrtf(re * re + im * im + 1e-4f) - 0.01f;
}

static __device__ __forceinline__ void q2c_mags(float v0x, float v0y, float v1x, float v1y,
                                                float& m_first, float& m_second) {
    const float s = 0.70710678118654752440f;
    float a = v0x * s, b = v0y * s, c = v1x * s, d = v1y * s;
    m_first  = smag(a - d, b + c);
    m_second = smag(a + d, b - c);
}

static __device__ __forceinline__ void fma4(float4& a, float c, const float4& v) {
    a.x += c * v.x; a.y += c * v.y; a.z += c * v.z; a.w += c * v.w;
}
static __device__ __forceinline__ void fma2(float2& a, float c, const float2& v) {
    a.x += c * v.x; a.y += c * v.y;
}

// Scratch: ll (96*512*512) and p (576*256*256)
__device__ float g_ll[25165824];
__device__ float g_p [37748736];

// ---------------------------------------------------------------------------
// j1 fused core: (global load + rowfilter) -> smem lo/hi -> col filter,
// 2 output rows per thread. Block (32,8). Out tile 16 rows x 64 pairs.
// Writer::lo(u, ll_row0, ll_row1, m0, m5) / Writer::hi(u, m1, m4, m2, m3)
// called for u = 0,1 (out rows 2ty+u of the tile).
// ---------------------------------------------------------------------------
template<int W, class Writer>
static __device__ __forceinline__ void j1_core2(
    const float* __restrict__ xim,
    const float* __restrict__ h0, const float* __restrict__ h1,
    int bx, int by, Writer& wr)
{
    __shared__ float slo[38][128];
    __shared__ float shi[38][128];

    const int tx = threadIdx.x, ty = threadIdx.y;
    const int tid = ty * 32 + tx;
    const int r0 = 32 * by - 3;
    const int c0 = 128 * bx - 4;

    float f0[5], f1[7];
#pragma unroll
    for (int k = 0; k < 5; k++) f0[k] = __ldg(h0 + k);
#pragma unroll
    for (int k = 0; k < 7; k++) f1[k] = __ldg(h1 + k);

    // ---- phase 1: fused global load + row filter: 38 rows x 32 quad-tasks ----
    for (int idx = tid; idx < 38 * 32; idx += 256) {
        int rr = idx >> 5, q = idx & 31;
        int c = c0 + 4 * q;
        const float* rowp = xim + (long)refl(r0 + rr, W) * W;
        float w[12];
        if (c >= 0 && c + 11 < W) {
            float4 A = *(const float4*)(rowp + c);
            float4 Bv = *(const float4*)(rowp + c + 4);
            float4 Cv = *(const float4*)(rowp + c + 8);
            w[0]=A.x; w[1]=A.y; w[2]=A.z; w[3]=A.w;
            w[4]=Bv.x; w[5]=Bv.y; w[6]=Bv.z; w[7]=Bv.w;
            w[8]=Cv.x; w[9]=Cv.y; w[10]=Cv.z; w[11]=Cv.w;
        } else {
#pragma unroll
            for (int j = 0; j < 12; j++) w[j] = rowp[refl(c + j, W)];
        }
        float o0[4], o1[4];
#pragma unroll
        for (int j = 0; j < 4; j++) {
            float s1 = 0.f;
#pragma unroll
            for (int k = 0; k < 7; k++) s1 += f1[k] * w[j + 1 + k];
            float s0 = 0.f;
#pragma unroll
            for (int k = 0; k < 5; k++) s0 += f0[k] * w[j + 2 + k];
            o0[j] = s0; o1[j] = s1;
        }
        ((float4*)slo[rr])[q] = make_float4(o0[0], o0[1], o0[2], o0[3]);
        ((float4*)shi[rr])[q] = make_float4(o1[0], o1[1], o1[2], o1[3]);
    }
    __syncthreads();

    // ---- phase 2a: lo branch (ll + lh), 2 out rows, stream 10 smem rows ----
    {
        float4 all0[2], all1[2], alh0[2], alh1[2];
#pragma unroll
        for (int u = 0; u < 2; u++) {
            all0[u] = make_float4(0,0,0,0); all1[u] = make_float4(0,0,0,0);
            alh0[u] = make_float4(0,0,0,0); alh1[u] = make_float4(0,0,0,0);
        }
#pragma unroll
        for (int r = 0; r < 10; r++) {
            float4 l = ((const float4*)slo[4 * ty + r])[tx];
#pragma unroll
            for (int u = 0; u < 2; u++) {
                int idx = r - 2 * u;
                if (idx < 0 || idx > 7) continue;
                if (idx <= 6) fma4(alh0[u], f1[idx], l);
                if (idx >= 1) fma4(alh1[u], f1[idx - 1], l);
                if (idx >= 1 && idx <= 5) fma4(all0[u], f0[idx - 1], l);
                if (idx >= 2 && idx <= 6) fma4(all1[u], f0[idx - 2], l);
            }
        }
#pragma unroll
        for (int u = 0; u < 2; u++) {
            float2 m0, m5;
            q2c_mags(alh0[u].x, alh0[u].y, alh1[u].x, alh1[u].y, m0.x, m5.x);
            q2c_mags(alh0[u].z, alh0[u].w, alh1[u].z, alh1[u].w, m0.y, m5.y);
            wr.lo(u, all0[u], all1[u], m0, m5);
        }
    }
    // ---- phase 2b: hi branch (hl + hh) ----
    {
        float4 ahl0[2], ahl1[2], ahh0[2], ahh1[2];
#pragma unroll
        for (int u = 0; u < 2; u++) {
            ahl0[u] = make_float4(0,0,0,0); ahl1[u] = make_float4(0,0,0,0);
            ahh0[u] = make_float4(0,0,0,0); ahh1[u] = make_float4(0,0,0,0);
        }
#pragma unroll
        for (int r = 0; r < 10; r++) {
            float4 h = ((const float4*)shi[4 * ty + r])[tx];
#pragma unroll
            for (int u = 0; u < 2; u++) {
                int idx = r - 2 * u;
                if (idx < 0 || idx > 7) continue;
                if (idx <= 6) fma4(ahh0[u], f1[idx], h);
                if (idx >= 1) fma4(ahh1[u], f1[idx - 1], h);
                if (idx >= 1 && idx <= 5) fma4(ahl0[u], f0[idx - 1], h);
                if (idx >= 2 && idx <= 6) fma4(ahl1[u], f0[idx - 2], h);
            }
        }
#pragma unroll
        for (int u = 0; u < 2; u++) {
            float2 m1, m4, m2, m3;
            q2c_mags(ahh0[u].x, ahh0[u].y, ahh1[u].x, ahh1[u].y, m1.x, m4.x);
            q2c_mags(ahh0[u].z, ahh0[u].w, ahh1[u].z, ahh1[u].w, m1.y, m4.y);
            q2c_mags(ahl0[u].x, ahl0[u].y, ahl1[u].x, ahl1[u].y, m2.x, m3.x);
            q2c_mags(ahl0[u].z, ahl0[u].w, ahl1[u].z, ahl1[u].w, m2.y, m3.y);
            wr.hi(u, m1, m4, m2, m3);
        }
    }
}

// ---------------------------------------------------------------------------
// Stage A writer + kernel. Grid (4,16,96), block (32,8).
// Ybase = 16by + 2ty; X = 64bx + 2tx; llc = 128bx + 4tx.
// ---------------------------------------------------------------------------
struct AWriter {
    float* llp0;  // ll row 2*Ybase at col llc
    float* pb;    // p at (b*18+ch) plane, row Ybase, col X
    __device__ __forceinline__ void lo(int u, float4 a, float4 bq, float2 m0, float2 m5) {
        *(float4*)(llp0 + u * 1024)       = a;
        *(float4*)(llp0 + u * 1024 + 512) = bq;
        *(float2*)(pb + u * 256)                      = m0;
        *(float2*)(pb + u * 256 + 5L * 196608)        = m5;
    }
    __device__ __forceinline__ void hi(int u, float2 m1, float2 m4, float2 m2, float2 m3) {
        *(float2*)(pb + u * 256 + 1L * 196608) = m1;
        *(float2*)(pb + u * 256 + 4L * 196608) = m4;
        *(float2*)(pb + u * 256 + 2L * 196608) = m2;
        *(float2*)(pb + u * 256 + 3L * 196608) = m3;
    }
};

__global__ __launch_bounds__(256, 4) void k_fusedA(
    const float* __restrict__ x,
    const float* __restrict__ h0, const float* __restrict__ h1,
    float* __restrict__ ll, float* __restrict__ p)
{
    const int bx = blockIdx.x, by = blockIdx.y, img = blockIdx.z;
    const int tx = threadIdx.x, ty = threadIdx.y;
    const int Ybase = 16 * by + 2 * ty;
    const int X = 64 * bx + 2 * tx;
    int b = img / 3, ch = img - 3 * b;

    AWriter wr;
    wr.llp0 = ll + (long)img * 262144 + (long)(2 * Ybase) * 512 + (128 * bx + 4 * tx);
    wr.pb   = p + ((long)b * 18 + ch) * 65536 + (long)Ybase * 256 + X;
    j1_core2<512>(x + (long)img * 262144, h0, h1, bx, by, wr);
}

// ---------------------------------------------------------------------------
// Stage C writer + kernel. Grid (2,8,576), block (32,8).
// ---------------------------------------------------------------------------
struct CWriter {
    float* zb;   // Z at (b,ch) base, row Ybase, col X
    int o1;
    __device__ __forceinline__ void lo(int u, float4 a, float4 bq, float2 m0, float2 m5) {
        float2 av = make_float2(0.25f * (a.x + a.y + bq.x + bq.y),
                                0.25f * (a.z + a.w + bq.z + bq.w));
        *(float2*)(zb + u * 128 + (long)(1 + o1) * 49152)  = av;
        *(float2*)(zb + u * 128 + (long)(13 + o1) * 49152) = m0;
        *(float2*)(zb + u * 128 + (long)(43 + o1) * 49152) = m5;
    }
    __device__ __forceinline__ void hi(int u, float2 m1, float2 m4, float2 m2, float2 m3) {
        *(float2*)(zb + u * 128 + (long)(19 + o1) * 49152) = m1;
        *(float2*)(zb + u * 128 + (long)(37 + o1) * 49152) = m4;
        *(float2*)(zb + u * 128 + (long)(25 + o1) * 49152) = m2;
        *(float2*)(zb + u * 128 + (long)(31 + o1) * 49152) = m3;
    }
};

__global__ __launch_bounds__(256, 4) void k_fusedC(
    const float* __restrict__ p,
    const float* __restrict__ h0, const float* __restrict__ h1,
    float* __restrict__ Z)
{
    const int bx = blockIdx.x, by = blockIdx.y, img = blockIdx.z;
    const int tx = threadIdx.x, ty = threadIdx.y;
    const int Ybase = 16 * by + 2 * ty;
    const int X = 64 * bx + 2 * tx;
    int b = img / 18;
    int c18 = img - 18 * b;
    int o1 = c18 / 3;
    int ch = c18 - 3 * o1;

    CWriter wr;
    wr.zb = Z + ((long)b * 147 + ch) * 16384 + (long)Ybase * 128 + X;
    wr.o1 = o1;
    j1_core2<256>(p + (long)img * 65536, h0, h1, bx, by, wr);
}

// ---------------------------------------------------------------------------
// Stage B: fused (load + rowdfilt) -> smem -> coldfilt (2 out rows/thread)
// + q2c + avgpool. Block (16,16): out tile 32Y x 16X. Grid (8,4,96).
// Z slots 0, 7..12.
// ---------------------------------------------------------------------------
__global__ __launch_bounds__(256, 4) void k_fusedB(
    const float* __restrict__ ll,
    const float* __restrict__ h0a, const float* __restrict__ h0b,
    const float* __restrict__ h1a, const float* __restrict__ h1b,
    float* __restrict__ Z)
{
    __shared__ float sl2[144][32];
    __shared__ float sh2[144][32];

    const int bx = blockIdx.x, by = blockIdx.y, img = blockIdx.z;
    const int tx = threadIdx.x, ty = threadIdx.y;
    const int tid = ty * 16 + tx;
    const float* lim = ll + (long)img * 262144;
    const int r0 = 128 * by - 8, c0 = 64 * bx - 8;

    float fa0[10], fb0[10], fa1[10], fb1[10];
#pragma unroll
    for (int k = 0; k < 10; k++) {
        fa0[k] = __ldg(h0a + k); fb0[k] = __ldg(h0b + k);
        fa1[k] = __ldg(h1a + k); fb1[k] = __ldg(h1b + k);
    }

    // ---- phase 1: fused load + rowdfilt. 144 rows x 8 quad-tasks ----
    for (int idx = tid; idx < 144 * 8; idx += 256) {
        int rr = idx >> 3, qq = idx & 7;
        int c = c0 + 8 * qq;
        const float* rowp = lim + (long)refl(r0 + rr, 512) * 512;
        float w[24];
        if (c >= 0 && c + 23 < 512) {
#pragma unroll
            for (int j = 0; j < 6; j++) {
                float4 v = *(const float4*)(rowp + c + 4 * j);
                w[4*j] = v.x; w[4*j+1] = v.y; w[4*j+2] = v.z; w[4*j+3] = v.w;
            }
        } else {
#pragma unroll
            for (int j = 0; j < 24; j++) w[j] = rowp[refl(c + j, 512)];
        }
        float lo_o[4], hi_o[4];
#pragma unroll
        for (int j = 0; j < 2; j++) {
            float se = 0.f, so = 0.f, te = 0.f, to = 0.f;
#pragma unroll
            for (int k = 0; k < 10; k++) {
                float ve = w[4 * j + 2 * k];
                float vo = w[4 * j + 1 + 2 * k];
                se += fb0[k] * ve;
                so += fa0[k] * vo;
                te += fa1[k] * vo;
                to += fb1[k] * ve;
            }
            lo_o[2*j] = se; lo_o[2*j+1] = so;
            hi_o[2*j] = te; hi_o[2*j+1] = to;
        }
        ((float4*)sl2[rr])[qq] = make_float4(lo_o[0], lo_o[1], lo_o[2], lo_o[3]);
        ((float4*)sh2[rr])[qq] = make_float4(hi_o[0], hi_o[1], hi_o[2], hi_o[3]);
    }
    __syncthreads();

    const int Ybase = 32 * by + 2 * ty, X = 16 * bx + tx;
    int b = img / 3, ch = img - 3 * b;
    float* zb = Z + ((long)b * 147 + ch) * 16384 + ((long)Ybase * 128 + X);

    // ---- phase 2a: lo branch (ll2 + lh2), 2 out rows, stream 12 row-pairs ----
    {
        float2 ll0[2], ll1[2], lh0[2], lh1[2];
#pragma unroll
        for (int u = 0; u < 2; u++) {
            ll0[u] = make_float2(0,0); ll1[u] = make_float2(0,0);
            lh0[u] = make_float2(0,0); lh1[u] = make_float2(0,0);
        }
#pragma unroll
        for (int j = 0; j < 12; j++) {
            int lrE = 8 * ty + 2 * j, lrO = lrE + 1;
            float2 a = ((const float2*)sl2[lrE])[tx];
            float2 q = ((const float2*)sl2[lrO])[tx];
#pragma unroll
            for (int u = 0; u < 2; u++) {
                int k = j - 2 * u;
                if (k < 0 || k > 9) continue;
                fma2(ll0[u], fb0[k], a);
                fma2(ll1[u], fa0[k], q);
                fma2(lh0[u], fa1[k], q);
                fma2(lh1[u], fb1[k], a);
            }
        }
#pragma unroll
        for (int u = 0; u < 2; u++) {
            float s0v = 0.25f * (ll0[u].x + ll0[u].y + ll1[u].x + ll1[u].y);
            float m0, m5;
            q2c_mags(lh0[u].x, lh0[u].y, lh1[u].x, lh1[u].y, m0, m5);
            zb[u * 128] = s0v;
            zb[u * 128 + 7L  * 49152] = m0;
            zb[u * 128 + 12L * 49152] = m5;
        }
    }
    // ---- phase 2b: hi branch (hl2 + hh2) ----
    {
        float2 hl0[2], hl1[2], hh0[2], hh1[2];
#pragma unroll
        for (int u = 0; u < 2; u++) {
            hl0[u] = make_float2(0,0); hl1[u] = make_float2(0,0);
            hh0[u] = make_float2(0,0); hh1[u] = make_float2(0,0);
        }
#pragma unroll
        for (int j = 0; j < 12; j++) {
            int lrE = 8 * ty + 2 * j, lrO = lrE + 1;
            float2 c = ((const float2*)sh2[lrE])[tx];
            float2 d = ((const float2*)sh2[lrO])[tx];
#pragma unroll
            for (int u = 0; u < 2; u++) {
                int k = j - 2 * u;
                if (k < 0 || k > 9) continue;
                fma2(hl0[u], fb0[k], c);
                fma2(hl1[u], fa0[k], d);
                fma2(hh0[u], fa1[k], d);
                fma2(hh1[u], fb1[k], c);
            }
        }
#pragma unroll
        for (int u = 0; u < 2; u++) {
            float m1, m4, m2, m3;
            q2c_mags(hh0[u].x, hh0[u].y, hh1[u].x, hh1[u].y, m1, m4);
            q2c_mags(hl0[u].x, hl0[u].y, hl1[u].x, hl1[u].y, m2, m3);
            zb[u * 128 + 8L  * 49152] = m1;
            zb[u * 128 + 11L * 49152] = m4;
            zb[u * 128 + 9L  * 49152] = m2;
            zb[u * 128 + 10L * 49152] = m3;
        }
    }
}

// ---------------------------------------------------------------------------
// Host launcher (graph-capturable)
// ---------------------------------------------------------------------------
extern "C" void kernel_launch(void* const* d_in, const int* in_sizes, int n_in,
                              void* d_out, int out_size)
{
    const float* x   = (const float*)d_in[0];
    const float* h0o = (const float*)d_in[1];
    const float* h1o = (const float*)d_in[2];
    const float* h0a = (const float*)d_in[3];
    const float* h0b = (const float*)d_in[4];
    const float* h1a = (const float*)d_in[5];
    const float* h1b = (const float*)d_in[6];
    float* Z = (float*)d_out;

    float *ll, *p;
    cudaGetSymbolAddress((void**)&ll, g_ll);
    cudaGetSymbolAddress((void**)&p,  g_p);

    k_fusedA<<<dim3(4, 16, 96),  dim3(32, 8)>>>(x, h0o, h1o, ll, p);
    k_fusedB<<<dim3(8, 4, 96),   dim3(16, 16)>>>(ll, h0a, h0b, h1a, h1b, Z);
    k_fusedC<<<dim3(2, 8, 576),  dim3(32, 8)>>>(p, h0o, h1o, Z);
}

// round 9
// speedup vs baseline: 2.4845x; 1.0049x over previous
#include <cuda_runtime.h>

// ---------------------------------------------------------------------------
// ScatLayerj2: 2-level DTCWT scattering. Fused, f32x2-packed math.
// x (32,3,512,512) f32 -> Z (32,147,128,128) f32
// ---------------------------------------------------------------------------

typedef unsigned long long u64;

static __device__ __forceinline__ u64 pk2(float lo, float hi) {
    u64 r; asm("mov.b64 %0,{%1,%2};" : "=l"(r) : "f"(lo), "f"(hi)); return r;
}
static __device__ __forceinline__ u64 bc2(float s) { return pk2(s, s); }
static __device__ __forceinline__ float2 upk(u64 v) {
    float2 r; asm("mov.b64 {%0,%1},%2;" : "=f"(r.x), "=f"(r.y) : "l"(v)); return r;
}
// d += a * b (per fp32 lane)
static __device__ __forceinline__ void fmap(u64& d, u64 a, u64 b) {
    asm("fma.rn.f32x2 %0,%1,%2,%0;" : "+l"(d) : "l"(a), "l"(b));
}

static __device__ __forceinline__ int refl(int p, int l) {
    if (p < 0)  p = -1 - p;
    if (p >= l) p = 2 * l - 1 - p;
    return p;
}

static __device__ __forceinline__ float smag(float re, float im) {
    return sqrtf(re * re + im * im + 1e-4f) - 0.01f;
}

static __device__ __forceinline__ void q2c_mags(float v0x, float v0y, float v1x, float v1y,
                                                float& m_first, float& m_second) {
    const float s = 0.70710678118654752440f;
    float a = v0x * s, b = v0y * s, c = v1x * s, d = v1y * s;
    m_first  = smag(a - d, b + c);
    m_second = smag(a + d, b - c);
}

// Scratch: ll (96*512*512) and p (576*256*256)
__device__ __align__(16) float g_ll[25165824];
__device__ __align__(16) float g_p [37748736];

// ---------------------------------------------------------------------------
// j1 fused core (packed): (load + rowfilter) -> smem lo/hi -> col filter,
// 2 output rows per thread. Block (32,8). Out tile 16 rows x 64 pairs.
// ---------------------------------------------------------------------------
template<int W, class Writer>
static __device__ __forceinline__ void j1_core2(
    const float* __restrict__ xim,
    const float* __restrict__ h0, const float* __restrict__ h1,
    int bx, int by, Writer& wr)
{
    __shared__ __align__(16) float slo[38][128];
    __shared__ __align__(16) float shi[38][128];

    const int tx = threadIdx.x, ty = threadIdx.y;
    const int tid = ty * 32 + tx;
    const int r0 = 32 * by - 3;
    const int c0 = 128 * bx - 4;

    u64 f0p[5], f1p[7];
#pragma unroll
    for (int k = 0; k < 5; k++) f0p[k] = bc2(__ldg(h0 + k));
#pragma unroll
    for (int k = 0; k < 7; k++) f1p[k] = bc2(__ldg(h1 + k));

    // ---- phase 1: fused load + row filter: 38 rows x 32 quad-tasks ----
    for (int idx = tid; idx < 38 * 32; idx += 256) {
        int rr = idx >> 5, q = idx & 31;
        int c = c0 + 4 * q;
        const float* rowp = xim + (long)refl(r0 + rr, W) * W;
        float w[12];
        if (c >= 0 && c + 11 < W) {
            float4 A = *(const float4*)(rowp + c);
            float4 Bv = *(const float4*)(rowp + c + 4);
            float4 Cv = *(const float4*)(rowp + c + 8);
            w[0]=A.x; w[1]=A.y; w[2]=A.z; w[3]=A.w;
            w[4]=Bv.x; w[5]=Bv.y; w[6]=Bv.z; w[7]=Bv.w;
            w[8]=Cv.x; w[9]=Cv.y; w[10]=Cv.z; w[11]=Cv.w;
        } else {
#pragma unroll
            for (int j = 0; j < 12; j++) w[j] = rowp[refl(c + j, W)];
        }
        u64 we[6], wo[5];
#pragma unroll
        for (int i = 0; i < 6; i++) we[i] = pk2(w[2*i], w[2*i+1]);
#pragma unroll
        for (int i = 0; i < 5; i++) wo[i] = pk2(w[2*i+1], w[2*i+2]);

        u64 a0[2], a1[2];
#pragma unroll
        for (int jp = 0; jp < 2; jp++) {
            u64 s1 = 0ull;
#pragma unroll
            for (int k = 0; k < 7; k++) {
                int b = 2 * jp + 1 + k;
                fmap(s1, f1p[k], (b & 1) ? wo[b >> 1] : we[b >> 1]);
            }
            u64 s0 = 0ull;
#pragma unroll
            for (int k = 0; k < 5; k++) {
                int b = 2 * jp + 2 + k;
                fmap(s0, f0p[k], (b & 1) ? wo[b >> 1] : we[b >> 1]);
            }
            a0[jp] = s0; a1[jp] = s1;
        }
        ((ulonglong2*)slo[rr])[q] = make_ulonglong2(a0[0], a0[1]);
        ((ulonglong2*)shi[rr])[q] = make_ulonglong2(a1[0], a1[1]);
    }
    __syncthreads();

    // ---- phase 2a: lo branch (ll + lh), 2 out rows, stream 10 smem rows ----
    {
        u64 aLL0[2][2], aLL1[2][2], aLH0[2][2], aLH1[2][2];
#pragma unroll
        for (int u = 0; u < 2; u++)
#pragma unroll
            for (int h = 0; h < 2; h++) {
                aLL0[u][h] = 0ull; aLL1[u][h] = 0ull;
                aLH0[u][h] = 0ull; aLH1[u][h] = 0ull;
            }
#pragma unroll
        for (int r = 0; r < 10; r++) {
            ulonglong2 l = ((const ulonglong2*)slo[4 * ty + r])[tx];
#pragma unroll
            for (int u = 0; u < 2; u++) {
                int idx = r - 2 * u;
                if (idx < 0 || idx > 7) continue;
                if (idx <= 6) { fmap(aLH0[u][0], f1p[idx], l.x); fmap(aLH0[u][1], f1p[idx], l.y); }
                if (idx >= 1) { fmap(aLH1[u][0], f1p[idx-1], l.x); fmap(aLH1[u][1], f1p[idx-1], l.y); }
                if (idx >= 1 && idx <= 5) { fmap(aLL0[u][0], f0p[idx-1], l.x); fmap(aLL0[u][1], f0p[idx-1], l.y); }
                if (idx >= 2 && idx <= 6) { fmap(aLL1[u][0], f0p[idx-2], l.x); fmap(aLL1[u][1], f0p[idx-2], l.y); }
            }
        }
#pragma unroll
        for (int u = 0; u < 2; u++) {
            float2 l00 = upk(aLL0[u][0]), l01 = upk(aLL0[u][1]);
            float2 l10 = upk(aLL1[u][0]), l11 = upk(aLL1[u][1]);
            float2 h00 = upk(aLH0[u][0]), h01 = upk(aLH0[u][1]);
            float2 h10 = upk(aLH1[u][0]), h11 = upk(aLH1[u][1]);
            float2 m0, m5;
            q2c_mags(h00.x, h00.y, h10.x, h10.y, m0.x, m5.x);
            q2c_mags(h01.x, h01.y, h11.x, h11.y, m0.y, m5.y);
            wr.lo(u, make_float4(l00.x, l00.y, l01.x, l01.y),
                     make_float4(l10.x, l10.y, l11.x, l11.y), m0, m5);
        }
    }
    // ---- phase 2b: hi branch (hl + hh) ----
    {
        u64 aHL0[2][2], aHL1[2][2], aHH0[2][2], aHH1[2][2];
#pragma unroll
        for (int u = 0; u < 2; u++)
#pragma unroll
            for (int h = 0; h < 2; h++) {
                aHL0[u][h] = 0ull; aHL1[u][h] = 0ull;
                aHH0[u][h] = 0ull; aHH1[u][h] = 0ull;
            }
#pragma unroll
        for (int r = 0; r < 10; r++) {
            ulonglong2 hv = ((const ulonglong2*)shi[4 * ty + r])[tx];
#pragma unroll
            for (int u = 0; u < 2; u++) {
                int idx = r - 2 * u;
                if (idx < 0 || idx > 7) continue;
                if (idx <= 6) { fmap(aHH0[u][0], f1p[idx], hv.x); fmap(aHH0[u][1], f1p[idx], hv.y); }
                if (idx >= 1) { fmap(aHH1[u][0], f1p[idx-1], hv.x); fmap(aHH1[u][1], f1p[idx-1], hv.y); }
                if (idx >= 1 && idx <= 5) { fmap(aHL0[u][0], f0p[idx-1], hv.x); fmap(aHL0[u][1], f0p[idx-1], hv.y); }
                if (idx >= 2 && idx <= 6) { fmap(aHL1[u][0], f0p[idx-2], hv.x); fmap(aHL1[u][1], f0p[idx-2], hv.y); }
            }
        }
#pragma unroll
        for (int u = 0; u < 2; u++) {
            float2 g00 = upk(aHH0[u][0]), g01 = upk(aHH0[u][1]);
            float2 g10 = upk(aHH1[u][0]), g11 = upk(aHH1[u][1]);
            float2 e00 = upk(aHL0[u][0]), e01 = upk(aHL0[u][1]);
            float2 e10 = upk(aHL1[u][0]), e11 = upk(aHL1[u][1]);
            float2 m1, m4, m2, m3;
            q2c_mags(g00.x, g00.y, g10.x, g10.y, m1.x, m4.x);
            q2c_mags(g01.x, g01.y, g11.x, g11.y, m1.y, m4.y);
            q2c_mags(e00.x, e00.y, e10.x, e10.y, m2.x, m3.x);
            q2c_mags(e01.x, e01.y, e11.x, e11.y, m2.y, m3.y);
            wr.hi(u, m1, m4, m2, m3);
        }
    }
}

// ---------------------------------------------------------------------------
// Stage A writer + kernel. Grid (4,16,96), block (32,8).
// ---------------------------------------------------------------------------
struct AWriter {
    float* llp0;
    float* pb;
    __device__ __forceinline__ void lo(int u, float4 a, float4 bq, float2 m0, float2 m5) {
        *(float4*)(llp0 + u * 1024)       = a;
        *(float4*)(llp0 + u * 1024 + 512) = bq;
        *(float2*)(pb + u * 256)               = m0;
        *(float2*)(pb + u * 256 + 5L * 196608) = m5;
    }
    __device__ __forceinline__ void hi(int u, float2 m1, float2 m4, float2 m2, float2 m3) {
        *(float2*)(pb + u * 256 + 1L * 196608) = m1;
        *(float2*)(pb + u * 256 + 4L * 196608) = m4;
        *(float2*)(pb + u * 256 + 2L * 196608) = m2;
        *(float2*)(pb + u * 256 + 3L * 196608) = m3;
    }
};

__global__ __launch_bounds__(256, 4) void k_fusedA(
    const float* __restrict__ x,
    const float* __restrict__ h0, const float* __restrict__ h1,
    float* __restrict__ ll, float* __restrict__ p)
{
    const int bx = blockIdx.x, by = blockIdx.y, img = blockIdx.z;
    const int tx = threadIdx.x, ty = threadIdx.y;
    const int Ybase = 16 * by + 2 * ty;
    const int X = 64 * bx + 2 * tx;
    int b = img / 3, ch = img - 3 * b;

    AWriter wr;
    wr.llp0 = ll + (long)img * 262144 + (long)(2 * Ybase) * 512 + (128 * bx + 4 * tx);
    wr.pb   = p + ((long)b * 18 + ch) * 65536 + (long)Ybase * 256 + X;
    j1_core2<512>(x + (long)img * 262144, h0, h1, bx, by, wr);
}

// ---------------------------------------------------------------------------
// Stage C writer + kernel. Grid (2,8,576), block (32,8).
// ---------------------------------------------------------------------------
struct CWriter {
    float* zb;
    int o1;
    __device__ __forceinline__ void lo(int u, float4 a, float4 bq, float2 m0, float2 m5) {
        float2 av = make_float2(0.25f * (a.x + a.y + bq.x + bq.y),
                                0.25f * (a.z + a.w + bq.z + bq.w));
        *(float2*)(zb + u * 128 + (long)(1 + o1) * 49152)  = av;
        *(float2*)(zb + u * 128 + (long)(13 + o1) * 49152) = m0;
        *(float2*)(zb + u * 128 + (long)(43 + o1) * 49152) = m5;
    }
    __device__ __forceinline__ void hi(int u, float2 m1, float2 m4, float2 m2, float2 m3) {
        *(float2*)(zb + u * 128 + (long)(19 + o1) * 49152) = m1;
        *(float2*)(zb + u * 128 + (long)(37 + o1) * 49152) = m4;
        *(float2*)(zb + u * 128 + (long)(25 + o1) * 49152) = m2;
        *(float2*)(zb + u * 128 + (long)(31 + o1) * 49152) = m3;
    }
};

__global__ __launch_bounds__(256, 4) void k_fusedC(
    const float* __restrict__ p,
    const float* __restrict__ h0, const float* __restrict__ h1,
    float* __restrict__ Z)
{
    const int bx = blockIdx.x, by = blockIdx.y, img = blockIdx.z;
    const int tx = threadIdx.x, ty = threadIdx.y;
    const int Ybase = 16 * by + 2 * ty;
    const int X = 64 * bx + 2 * tx;
    int b = img / 18;
    int c18 = img - 18 * b;
    int o1 = c18 / 3;
    int ch = c18 - 3 * o1;

    CWriter wr;
    wr.zb = Z + ((long)b * 147 + ch) * 16384 + (long)Ybase * 128 + X;
    wr.o1 = o1;
    j1_core2<256>(p + (long)img * 65536, h0, h1, bx, by, wr);
}

// ---------------------------------------------------------------------------
// Stage B: fused (load + rowdfilt) -> smem -> coldfilt (2 out rows/thread)
// + q2c + avgpool, f32x2-packed. Block (16,16): out tile 32Y x 16X. Grid (8,4,96).
// ---------------------------------------------------------------------------
__global__ __launch_bounds__(256, 4) void k_fusedB(
    const float* __restrict__ ll,
    const float* __restrict__ h0a, const float* __restrict__ h0b,
    const float* __restrict__ h1a, const float* __restrict__ h1b,
    float* __restrict__ Z)
{
    __shared__ __align__(16) float sl2[144][32];
    __shared__ __align__(16) float sh2[144][32];

    const int bx = blockIdx.x, by = blockIdx.y, img = blockIdx.z;
    const int tx = threadIdx.x, ty = threadIdx.y;
    const int tid = ty * 16 + tx;
    const float* lim = ll + (long)img * 262144;
    const int r0 = 128 * by - 8, c0 = 64 * bx - 8;

    float fa0[10], fb0[10], fa1[10], fb1[10];
#pragma unroll
    for (int k = 0; k < 10; k++) {
        fa0[k] = __ldg(h0a + k); fb0[k] = __ldg(h0b + k);
        fa1[k] = __ldg(h1a + k); fb1[k] = __ldg(h1b + k);
    }

    // ---- phase 1: fused load + rowdfilt, packed. 144 rows x 8 quad-tasks ----
    // w2[i] = (w[2i], w[2i+1]); operand for (j,k) = w2[2j+k].
    //   accL[j] = (se, so) with coeff (fb0[k], fa0[k])
    //   accH[j] = (to, te) with coeff (fb1[k], fa1[k])  -> out (te, to)
    for (int idx = tid; idx < 144 * 8; idx += 256) {
        int rr = idx >> 3, qq = idx & 7;
        int c = c0 + 8 * qq;
        const float* rowp = lim + (long)refl(r0 + rr, 512) * 512;
        u64 w2[12];
        if (c >= 0 && c + 23 < 512) {
            const ulonglong2* rv = (const ulonglong2*)(rowp + c);
#pragma unroll
            for (int j = 0; j < 6; j++) {
                ulonglong2 v = rv[j];
                w2[2*j] = v.x; w2[2*j+1] = v.y;
            }
        } else {
            float w[24];
#pragma unroll
            for (int j = 0; j < 24; j++) w[j] = rowp[refl(c + j, 512)];
#pragma unroll
            for (int i = 0; i < 12; i++) w2[i] = pk2(w[2*i], w[2*i+1]);
        }
        u64 accL[2] = {0ull, 0ull}, accH[2] = {0ull, 0ull};
#pragma unroll
        for (int k = 0; k < 10; k++) {
            u64 cl = pk2(fb0[k], fa0[k]);
            u64 ch = pk2(fb1[k], fa1[k]);
#pragma unroll
            for (int j = 0; j < 2; j++) {
                fmap(accL[j], cl, w2[2*j + k]);
                fmap(accH[j], ch, w2[2*j + k]);
            }
        }
        float2 L0 = upk(accL[0]), L1 = upk(accL[1]);
        float2 H0 = upk(accH[0]), H1 = upk(accH[1]);
        ((float4*)sl2[rr])[qq] = make_float4(L0.x, L0.y, L1.x, L1.y);
        ((float4*)sh2[rr])[qq] = make_float4(H0.y, H0.x, H1.y, H1.x);
    }
    __syncthreads();

    const int Ybase = 32 * by + 2 * ty, X = 16 * bx + tx;
    int b = img / 3, ch = img - 3 * b;
    float* zb = Z + ((long)b * 147 + ch) * 16384 + ((long)Ybase * 128 + X);

    // ---- phase 2a: lo branch (ll2 + lh2), packed ----
    {
        u64 ll0[2] = {0,0}, ll1[2] = {0,0}, lh0[2] = {0,0}, lh1[2] = {0,0};
#pragma unroll
        for (int j = 0; j < 12; j++) {
            int lrE = 8 * ty + 2 * j, lrO = lrE + 1;
            u64 a = ((const u64*)sl2[lrE])[tx];
            u64 q = ((const u64*)sl2[lrO])[tx];
#pragma unroll
            for (int u = 0; u < 2; u++) {
                int k = j - 2 * u;
                if (k < 0 || k > 9) continue;
                fmap(ll0[u], bc2(fb0[k]), a);
                fmap(ll1[u], bc2(fa0[k]), q);
                fmap(lh0[u], bc2(fa1[k]), q);
                fmap(lh1[u], bc2(fb1[k]), a);
            }
        }
#pragma unroll
        for (int u = 0; u < 2; u++) {
            float2 L0 = upk(ll0[u]), L1 = upk(ll1[u]);
            float2 G0 = upk(lh0[u]), G1 = upk(lh1[u]);
            float s0v = 0.25f * (L0.x + L0.y + L1.x + L1.y);
            float m0, m5;
            q2c_mags(G0.x, G0.y, G1.x, G1.y, m0, m5);
            zb[u * 128] = s0v;
            zb[u * 128 + 7L  * 49152] = m0;
            zb[u * 128 + 12L * 49152] = m5;
        }
    }
    // ---- phase 2b: hi branch (hl2 + hh2), packed ----
    {
        u64 hl0[2] = {0,0}, hl1[2] = {0,0}, hh0[2] = {0,0}, hh1[2] = {0,0};
#pragma unroll
        for (int j = 0; j < 12; j++) {
            int lrE = 8 * ty + 2 * j, lrO = lrE + 1;
            u64 cv = ((const u64*)sh2[lrE])[tx];
            u64 dv = ((const u64*)sh2[lrO])[tx];
#pragma unroll
            for (int u = 0; u < 2; u++) {
                int k = j - 2 * u;
                if (k < 0 || k > 9) continue;
                fmap(hl0[u], bc2(fb0[k]), cv);
                fmap(hl1[u], bc2(fa0[k]), dv);
                fmap(hh0[u], bc2(fa1[k]), dv);
                fmap(hh1[u], bc2(fb1[k]), cv);
            }
        }
#pragma unroll
        for (int u = 0; u < 2; u++) {
            float2 E0 = upk(hl0[u]), E1 = upk(hl1[u]);
            float2 G0 = upk(hh0[u]), G1 = upk(hh1[u]);
            float m1, m4, m2, m3;
            q2c_mags(G0.x, G0.y, G1.x, G1.y, m1, m4);
            q2c_mags(E0.x, E0.y, E1.x, E1.y, m2, m3);
            zb[u * 128 + 8L  * 49152] = m1;
            zb[u * 128 + 11L * 49152] = m4;
            zb[u * 128 + 9L  * 49152] = m2;
            zb[u * 128 + 10L * 49152] = m3;
        }
    }
}

// ---------------------------------------------------------------------------
// Host launcher (graph-capturable)
// ---------------------------------------------------------------------------
extern "C" void kernel_launch(void* const* d_in, const int* in_sizes, int n_in,
                              void* d_out, int out_size)
{
    const float* x   = (const float*)d_in[0];
    const float* h0o = (const float*)d_in[1];
    const float* h1o = (const float*)d_in[2];
    const float* h0a = (const float*)d_in[3];
    const float* h0b = (const float*)d_in[4];
    const float* h1a = (const float*)d_in[5];
    const float* h1b = (const float*)d_in[6];
    float* Z = (float*)d_out;

    float *ll, *p;
    cudaGetSymbolAddress((void**)&ll, g_ll);
    cudaGetSymbolAddress((void**)&p,  g_p);

    k_fusedA<<<dim3(4, 16, 96),  dim3(32, 8)>>>(x, h0o, h1o, ll, p);
    k_fusedB<<<dim3(8, 4, 96),   dim3(16, 16)>>>(ll, h0a, h0b, h1a, h1b, Z);
    k_fusedC<<<dim3(2, 8, 576),  dim3(32, 8)>>>(p, h0o, h1o, Z);
}

// round 11
// speedup vs baseline: 2.5052x; 1.0083x over previous
#include <cuda_runtime.h>

// ---------------------------------------------------------------------------
// ScatLayerj2: 2-level DTCWT scattering. Fused; A/C tuned for occupancy.
// x (32,3,512,512) f32 -> Z (32,147,128,128) f32
// ---------------------------------------------------------------------------

typedef unsigned long long u64;

static __device__ __forceinline__ u64 pk2(float lo, float hi) {
    u64 r; asm("mov.b64 %0,{%1,%2};" : "=l"(r) : "f"(lo), "f"(hi)); return r;
}
static __device__ __forceinline__ float2 upk(u64 v) {
    float2 r; asm("mov.b64 {%0,%1},%2;" : "=f"(r.x), "=f"(r.y) : "l"(v)); return r;
}
static __device__ __forceinline__ u64 bc2(float s) { return pk2(s, s); }
static __device__ __forceinline__ void fmap(u64& d, u64 a, u64 b) {
    asm("fma.rn.f32x2 %0,%1,%2,%0;" : "+l"(d) : "l"(a), "l"(b));
}

static __device__ __forceinline__ int refl(int p, int l) {
    if (p < 0)  p = -1 - p;
    if (p >= l) p = 2 * l - 1 - p;
    return p;
}

static __device__ __forceinline__ float smag(float re, float im) {
    return sqrtf(re * re + im * im + 1e-4f) - 0.01f;
}

static __device__ __forceinline__ void q2c_mags(float v0x, float v0y, float v1x, float v1y,
                                                float& m_first, float& m_second) {
    const float s = 0.70710678118654752440f;
    float a = v0x * s, b = v0y * s, c = v1x * s, d = v1y * s;
    m_first  = smag(a - d, b + c);
    m_second = smag(a + d, b - c);
}

// Scratch: ll (96*512*512) and p (576*256*256)
__device__ __align__(16) float g_ll[25165824];
__device__ __align__(16) float g_p [37748736];

// ---------------------------------------------------------------------------
// j1 fused core, 2px/thread: (load + rowfilter, scalar) -> smem lo/hi ->
// split col filter (2 out rows/thread, float2). Block (32,8).
// Out tile: 16 pair-rows x 32 pairs (64 px). smem tile 38 x 64.
// ---------------------------------------------------------------------------
template<int W, class Writer>
static __device__ __forceinline__ void j1_core2(
    const float* __restrict__ xim,
    const float* __restrict__ h0, const float* __restrict__ h1,
    int bx, int by, Writer& wr)
{
    __shared__ __align__(16) float slo[38][64];
    __shared__ __align__(16) float shi[38][64];

    const int tx = threadIdx.x, ty = threadIdx.y;
    const int tid = ty * 32 + tx;
    const int r0 = 32 * by - 3;
    const int c0 = 64 * bx - 4;

    float f0[5], f1[7];
#pragma unroll
    for (int k = 0; k < 5; k++) f0[k] = __ldg(h0 + k);
#pragma unroll
    for (int k = 0; k < 7; k++) f1[k] = __ldg(h1 + k);

    // ---- phase 1 (scalar): fused load + row filter. 38 rows x 16 quad-tasks ----
    for (int idx = tid; idx < 38 * 16; idx += 256) {
        int rr = idx >> 4, q = idx & 15;
        int c = c0 + 4 * q;
        const float* rowp = xim + (long)refl(r0 + rr, W) * W;
        float w[12];
        if (c >= 0 && c + 11 < W) {
            float4 A = *(const float4*)(rowp + c);
            float4 Bv = *(const float4*)(rowp + c + 4);
            float4 Cv = *(const float4*)(rowp + c + 8);
            w[0]=A.x; w[1]=A.y; w[2]=A.z; w[3]=A.w;
            w[4]=Bv.x; w[5]=Bv.y; w[6]=Bv.z; w[7]=Bv.w;
            w[8]=Cv.x; w[9]=Cv.y; w[10]=Cv.z; w[11]=Cv.w;
        } else {
#pragma unroll
            for (int j = 0; j < 12; j++) w[j] = rowp[refl(c + j, W)];
        }
        float o0[4], o1[4];
#pragma unroll
        for (int j = 0; j < 4; j++) {
            float s1 = 0.f;
#pragma unroll
            for (int k = 0; k < 7; k++) s1 += f1[k] * w[j + 1 + k];
            float s0 = 0.f;
#pragma unroll
            for (int k = 0; k < 5; k++) s0 += f0[k] * w[j + 2 + k];
            o0[j] = s0; o1[j] = s1;
        }
        ((float4*)slo[rr])[q] = make_float4(o0[0], o0[1], o0[2], o0[3]);
        ((float4*)shi[rr])[q] = make_float4(o1[0], o1[1], o1[2], o1[3]);
    }
    __syncthreads();

    // ---- phase 2a: lo branch (ll + lh), 2 out rows, stream 10 smem rows ----
    {
        float2 ll0[2], ll1[2], lh0[2], lh1[2];
#pragma unroll
        for (int u = 0; u < 2; u++) {
            ll0[u] = make_float2(0,0); ll1[u] = make_float2(0,0);
            lh0[u] = make_float2(0,0); lh1[u] = make_float2(0,0);
        }
#pragma unroll
        for (int r = 0; r < 10; r++) {
            float2 l = ((const float2*)slo[4 * ty + r])[tx];
#pragma unroll
            for (int u = 0; u < 2; u++) {
                int idx = r - 2 * u;
                if (idx < 0 || idx > 7) continue;
                if (idx <= 6)             { lh0[u].x += f1[idx]*l.x;   lh0[u].y += f1[idx]*l.y; }
                if (idx >= 1)             { lh1[u].x += f1[idx-1]*l.x; lh1[u].y += f1[idx-1]*l.y; }
                if (idx >= 1 && idx <= 5) { ll0[u].x += f0[idx-1]*l.x; ll0[u].y += f0[idx-1]*l.y; }
                if (idx >= 2 && idx <= 6) { ll1[u].x += f0[idx-2]*l.x; ll1[u].y += f0[idx-2]*l.y; }
            }
        }
#pragma unroll
        for (int u = 0; u < 2; u++) {
            float m0, m5;
            q2c_mags(lh0[u].x, lh0[u].y, lh1[u].x, lh1[u].y, m0, m5);
            wr.lo(u, ll0[u], ll1[u], m0, m5);
        }
    }
    // ---- phase 2b: hi branch (hl + hh) ----
    {
        float2 hl0[2], hl1[2], hh0[2], hh1[2];
#pragma unroll
        for (int u = 0; u < 2; u++) {
            hl0[u] = make_float2(0,0); hl1[u] = make_float2(0,0);
            hh0[u] = make_float2(0,0); hh1[u] = make_float2(0,0);
        }
#pragma unroll
        for (int r = 0; r < 10; r++) {
            float2 h = ((const float2*)shi[4 * ty + r])[tx];
#pragma unroll
            for (int u = 0; u < 2; u++) {
                int idx = r - 2 * u;
                if (idx < 0 || idx > 7) continue;
                if (idx <= 6)             { hh0[u].x += f1[idx]*h.x;   hh0[u].y += f1[idx]*h.y; }
                if (idx >= 1)             { hh1[u].x += f1[idx-1]*h.x; hh1[u].y += f1[idx-1]*h.y; }
                if (idx >= 1 && idx <= 5) { hl0[u].x += f0[idx-1]*h.x; hl0[u].y += f0[idx-1]*h.y; }
                if (idx >= 2 && idx <= 6) { hl1[u].x += f0[idx-2]*h.x; hl1[u].y += f0[idx-2]*h.y; }
            }
        }
#pragma unroll
        for (int u = 0; u < 2; u++) {
            float m1, m4, m2, m3;
            q2c_mags(hh0[u].x, hh0[u].y, hh1[u].x, hh1[u].y, m1, m4);
            q2c_mags(hl0[u].x, hl0[u].y, hl1[u].x, hl1[u].y, m2, m3);
            wr.hi(u, m1, m4, m2, m3);
        }
    }
}

// ---------------------------------------------------------------------------
// Stage A writer + kernel. Grid (8,16,96), block (32,8).
// Ybase = 16by + 2ty (pair-row), pair col Xp = 32bx + tx, px col 64bx + 2tx.
// ---------------------------------------------------------------------------
struct AWriter {
    float* llp0;  // ll row 2*Ybase at px col
    float* pb;    // p plane (b*18+ch), row Ybase, col Xp
    __device__ __forceinline__ void lo(int u, float2 a, float2 bq, float m0, float m5) {
        *(float2*)(llp0 + u * 1024)       = a;
        *(float2*)(llp0 + u * 1024 + 512) = bq;
        pb[u * 256]               = m0;
        pb[u * 256 + 5L * 196608] = m5;
    }
    __device__ __forceinline__ void hi(int u, float m1, float m4, float m2, float m3) {
        pb[u * 256 + 1L * 196608] = m1;
        pb[u * 256 + 4L * 196608] = m4;
        pb[u * 256 + 2L * 196608] = m2;
        pb[u * 256 + 3L * 196608] = m3;
    }
};

__global__ __launch_bounds__(256, 5) void k_fusedA(
    const float* __restrict__ x,
    const float* __restrict__ h0, const float* __restrict__ h1,
    float* __restrict__ ll, float* __restrict__ p)
{
    const int bx = blockIdx.x, by = blockIdx.y, img = blockIdx.z;
    const int tx = threadIdx.x, ty = threadIdx.y;
    const int Ybase = 16 * by + 2 * ty;
    int b = img / 3, ch = img - 3 * b;

    AWriter wr;
    wr.llp0 = ll + (long)img * 262144 + (long)(2 * Ybase) * 512 + (64 * bx + 2 * tx);
    wr.pb   = p + ((long)b * 18 + ch) * 65536 + (long)Ybase * 256 + (32 * bx + tx);
    j1_core2<512>(x + (long)img * 262144, h0, h1, bx, by, wr);
}

// ---------------------------------------------------------------------------
// Stage C writer + kernel. Grid (4,8,576), block (32,8).
// ---------------------------------------------------------------------------
struct CWriter {
    float* zb;   // Z (b,ch) base, row Ybase, col Xp
    int o1;
    __device__ __forceinline__ void lo(int u, float2 a, float2 bq, float m0, float m5) {
        float av = 0.25f * (a.x + a.y + bq.x + bq.y);
        zb[u * 128 + (long)(1 + o1) * 49152]  = av;
        zb[u * 128 + (long)(13 + o1) * 49152] = m0;
        zb[u * 128 + (long)(43 + o1) * 49152] = m5;
    }
    __device__ __forceinline__ void hi(int u, float m1, float m4, float m2, float m3) {
        zb[u * 128 + (long)(19 + o1) * 49152] = m1;
        zb[u * 128 + (long)(37 + o1) * 49152] = m4;
        zb[u * 128 + (long)(25 + o1) * 49152] = m2;
        zb[u * 128 + (long)(31 + o1) * 49152] = m3;
    }
};

__global__ __launch_bounds__(256, 5) void k_fusedC(
    const float* __restrict__ p,
    const float* __restrict__ h0, const float* __restrict__ h1,
    float* __restrict__ Z)
{
    const int bx = blockIdx.x, by = blockIdx.y, img = blockIdx.z;
    const int tx = threadIdx.x, ty = threadIdx.y;
    const int Ybase = 16 * by + 2 * ty;
    int b = img / 18;
    int c18 = img - 18 * b;
    int o1 = c18 / 3;
    int ch = c18 - 3 * o1;

    CWriter wr;
    wr.zb = Z + ((long)b * 147 + ch) * 16384 + (long)Ybase * 128 + (32 * bx + tx);
    wr.o1 = o1;
    j1_core2<256>(p + (long)img * 65536, h0, h1, bx, by, wr);
}

// ---------------------------------------------------------------------------
// Stage B: fused (load + rowdfilt) -> smem -> coldfilt (2 out rows/thread)
// + q2c + avgpool, f32x2-packed. Block (16,16): out tile 32Y x 16X. Grid (8,4,96).
// ---------------------------------------------------------------------------
__global__ __launch_bounds__(256, 4) void k_fusedB(
    const float* __restrict__ ll,
    const float* __restrict__ h0a, const float* __restrict__ h0b,
    const float* __restrict__ h1a, const float* __restrict__ h1b,
    float* __restrict__ Z)
{
    __shared__ __align__(16) float sl2[144][32];
    __shared__ __align__(16) float sh2[144][32];

    const int bx = blockIdx.x, by = blockIdx.y, img = blockIdx.z;
    const int tx = threadIdx.x, ty = threadIdx.y;
    const int tid = ty * 16 + tx;
    const float* lim = ll + (long)img * 262144;
    const int r0 = 128 * by - 8, c0 = 64 * bx - 8;

    float fa0[10], fb0[10], fa1[10], fb1[10];
#pragma unroll
    for (int k = 0; k < 10; k++) {
        fa0[k] = __ldg(h0a + k); fb0[k] = __ldg(h0b + k);
        fa1[k] = __ldg(h1a + k); fb1[k] = __ldg(h1b + k);
    }

    // ---- phase 1: fused load + rowdfilt, packed. 144 rows x 8 quad-tasks ----
    for (int idx = tid; idx < 144 * 8; idx += 256) {
        int rr = idx >> 3, qq = idx & 7;
        int c = c0 + 8 * qq;
        const float* rowp = lim + (long)refl(r0 + rr, 512) * 512;
        u64 w2[12];
        if (c >= 0 && c + 23 < 512) {
            const ulonglong2* rv = (const ulonglong2*)(rowp + c);
#pragma unroll
            for (int j = 0; j < 6; j++) {
                ulonglong2 v = rv[j];
                w2[2*j] = v.x; w2[2*j+1] = v.y;
            }
        } else {
            float w[24];
#pragma unroll
            for (int j = 0; j < 24; j++) w[j] = rowp[refl(c + j, 512)];
#pragma unroll
            for (int i = 0; i < 12; i++) w2[i] = pk2(w[2*i], w[2*i+1]);
        }
        u64 accL[2] = {0ull, 0ull}, accH[2] = {0ull, 0ull};
#pragma unroll
        for (int k = 0; k < 10; k++) {
            u64 cl = pk2(fb0[k], fa0[k]);
            u64 ch = pk2(fb1[k], fa1[k]);
#pragma unroll
            for (int j = 0; j < 2; j++) {
                fmap(accL[j], cl, w2[2*j + k]);
                fmap(accH[j], ch, w2[2*j + k]);
            }
        }
        float2 L0 = upk(accL[0]), L1 = upk(accL[1]);
        float2 H0 = upk(accH[0]), H1 = upk(accH[1]);
        ((float4*)sl2[rr])[qq] = make_float4(L0.x, L0.y, L1.x, L1.y);
        ((float4*)sh2[rr])[qq] = make_float4(H0.y, H0.x, H1.y, H1.x);
    }
    __syncthreads();

    const int Ybase = 32 * by + 2 * ty, X = 16 * bx + tx;
    int b = img / 3, ch = img - 3 * b;
    float* zb = Z + ((long)b * 147 + ch) * 16384 + ((long)Ybase * 128 + X);

    // ---- phase 2a: lo branch (ll2 + lh2), packed ----
    {
        u64 ll0[2] = {0,0}, ll1[2] = {0,0}, lh0[2] = {0,0}, lh1[2] = {0,0};
#pragma unroll
        for (int j = 0; j < 12; j++) {
            int lrE = 8 * ty + 2 * j, lrO = lrE + 1;
            u64 a = ((const u64*)sl2[lrE])[tx];
            u64 q = ((const u64*)sl2[lrO])[tx];
#pragma unroll
            for (int u = 0; u < 2; u++) {
                int k = j - 2 * u;
                if (k < 0 || k > 9) continue;
                fmap(ll0[u], bc2(fb0[k]), a);
                fmap(ll1[u], bc2(fa0[k]), q);
                fmap(lh0[u], bc2(fa1[k]), q);
                fmap(lh1[u], bc2(fb1[k]), a);
            }
        }
#pragma unroll
        for (int u = 0; u < 2; u++) {
            float2 L0 = upk(ll0[u]), L1 = upk(ll1[u]);
            float2 G0 = upk(lh0[u]), G1 = upk(lh1[u]);
            float s0v = 0.25f * (L0.x + L0.y + L1.x + L1.y);
            float m0, m5;
            q2c_mags(G0.x, G0.y, G1.x, G1.y, m0, m5);
            zb[u * 128] = s0v;
            zb[u * 128 + 7L  * 49152] = m0;
            zb[u * 128 + 12L * 49152] = m5;
        }
    }
    // ---- phase 2b: hi branch (hl2 + hh2), packed ----
    {
        u64 hl0[2] = {0,0}, hl1[2] = {0,0}, hh0[2] = {0,0}, hh1[2] = {0,0};
#pragma unroll
        for (int j = 0; j < 12; j++) {
            int lrE = 8 * ty + 2 * j, lrO = lrE + 1;
            u64 cv = ((const u64*)sh2[lrE])[tx];
            u64 dv = ((const u64*)sh2[lrO])[tx];
#pragma unroll
            for (int u = 0; u < 2; u++) {
                int k = j - 2 * u;
                if (k < 0 || k > 9) continue;
                fmap(hl0[u], bc2(fb0[k]), cv);
                fmap(hl1[u], bc2(fa0[k]), dv);
                fmap(hh0[u], bc2(fa1[k]), dv);
                fmap(hh1[u], bc2(fb1[k]), cv);
            }
        }
#pragma unroll
        for (int u = 0; u < 2; u++) {
            float2 E0 = upk(hl0[u]), E1 = upk(hl1[u]);
            float2 G0 = upk(hh0[u]), G1 = upk(hh1[u]);
            float m1, m4, m2, m3;
            q2c_mags(G0.x, G0.y, G1.x, G1.y, m1, m4);
            q2c_mags(E0.x, E0.y, E1.x, E1.y, m2, m3);
            zb[u * 128 + 8L  * 49152] = m1;
            zb[u * 128 + 11L * 49152] = m4;
            zb[u * 128 + 9L  * 49152] = m2;
            zb[u * 128 + 10L * 49152] = m3;
        }
    }
}

// ---------------------------------------------------------------------------
// Host launcher (graph-capturable)
// ---------------------------------------------------------------------------
extern "C" void kernel_launch(void* const* d_in, const int* in_sizes, int n_in,
                              void* d_out, int out_size)
{
    const float* x   = (const float*)d_in[0];
    const float* h0o = (const float*)d_in[1];
    const float* h1o = (const float*)d_in[2];
    const float* h0a = (const float*)d_in[3];
    const float* h0b = (const float*)d_in[4];
    const float* h1a = (const float*)d_in[5];
    const float* h1b = (const float*)d_in[6];
    float* Z = (float*)d_out;

    float *ll, *p;
    cudaGetSymbolAddress((void**)&ll, g_ll);
    cudaGetSymbolAddress((void**)&p,  g_p);

    k_fusedA<<<dim3(8, 16, 96), dim3(32, 8)>>>(x, h0o, h1o, ll, p);
    k_fusedB<<<dim3(8, 4, 96),  dim3(16, 16)>>>(ll, h0a, h0b, h1a, h1b, Z);
    k_fusedC<<<dim3(4, 8, 576), dim3(32, 8)>>>(p, h0o, h1o, Z);
}

// round 12
// speedup vs baseline: 2.5295x; 1.0097x over previous
#include <cuda_runtime.h>
#include <cuda_fp16.h>

// ---------------------------------------------------------------------------
// ScatLayerj2: 2-level DTCWT scattering. Fused; fp16 intermediates; packed
// f32x2 column filters. x (32,3,512,512) f32 -> Z (32,147,128,128) f32
// ---------------------------------------------------------------------------

typedef unsigned long long u64;

static __device__ __forceinline__ u64 pk2(float lo, float hi) {
    u64 r; asm("mov.b64 %0,{%1,%2};" : "=l"(r) : "f"(lo), "f"(hi)); return r;
}
static __device__ __forceinline__ float2 upk(u64 v) {
    float2 r; asm("mov.b64 {%0,%1},%2;" : "=f"(r.x), "=f"(r.y) : "l"(v)); return r;
}
static __device__ __forceinline__ u64 bc2(float s) { return pk2(s, s); }
static __device__ __forceinline__ void fmap(u64& d, u64 a, u64 b) {
    asm("fma.rn.f32x2 %0,%1,%2,%0;" : "+l"(d) : "l"(a), "l"(b));
}

static __device__ __forceinline__ int refl(int p, int l) {
    if (p < 0)  p = -1 - p;
    if (p >= l) p = 2 * l - 1 - p;
    return p;
}

static __device__ __forceinline__ float smag(float re, float im) {
    return sqrtf(re * re + im * im + 1e-4f) - 0.01f;
}

static __device__ __forceinline__ void q2c_mags(float v0x, float v0y, float v1x, float v1y,
                                                float& m_first, float& m_second) {
    const float s = 0.70710678118654752440f;
    float a = v0x * s, b = v0y * s, c = v1x * s, d = v1y * s;
    m_first  = smag(a - d, b + c);
    m_second = smag(a + d, b - c);
}

static __device__ __forceinline__ float to_f(float v)  { return v; }
static __device__ __forceinline__ float to_f(__half v) { return __half2float(v); }

// 12-wide window loaders (interior, aligned to 4 elements)
static __device__ __forceinline__ void load12(const float* rowp, int c, float* w) {
    float4 A = *(const float4*)(rowp + c);
    float4 B = *(const float4*)(rowp + c + 4);
    float4 C = *(const float4*)(rowp + c + 8);
    w[0]=A.x; w[1]=A.y; w[2]=A.z; w[3]=A.w;
    w[4]=B.x; w[5]=B.y; w[6]=B.z; w[7]=B.w;
    w[8]=C.x; w[9]=C.y; w[10]=C.z; w[11]=C.w;
}
static __device__ __forceinline__ void load12(const __half* rowp, int c, float* w) {
    uint2 a = *(const uint2*)(rowp + c);
    uint2 b = *(const uint2*)(rowp + c + 4);
    uint2 d = *(const uint2*)(rowp + c + 8);
    const __half2* ha = (const __half2*)&a;
    const __half2* hb = (const __half2*)&b;
    const __half2* hd = (const __half2*)&d;
#pragma unroll
    for (int i = 0; i < 2; i++) {
        float2 f0 = __half22float2(ha[i]); w[2*i]   = f0.x; w[2*i+1]   = f0.y;
        float2 f1 = __half22float2(hb[i]); w[4+2*i] = f1.x; w[4+2*i+1] = f1.y;
        float2 f2 = __half22float2(hd[i]); w[8+2*i] = f2.x; w[8+2*i+1] = f2.y;
    }
}

// Scratch (fp16): ll (96*512*512) and p (576*256*256)
__device__ __align__(16) __half g_ll[25165824];
__device__ __align__(16) __half g_p [37748736];

// ---------------------------------------------------------------------------
// j1 fused core, 2px/thread: (load + rowfilter, scalar) -> smem lo/hi ->
// split col filter (2 out rows/thread, packed f32x2). Block (32,8).
// Out tile: 16 pair-rows x 32 pairs (64 px). smem tile 38 x 64.
// ---------------------------------------------------------------------------
template<int W, typename T, class Writer>
static __device__ __forceinline__ void j1_core2(
    const T* __restrict__ xim,
    const float* __restrict__ h0, const float* __restrict__ h1,
    int bx, int by, Writer& wr)
{
    __shared__ __align__(16) float slo[38][64];
    __shared__ __align__(16) float shi[38][64];

    const int tx = threadIdx.x, ty = threadIdx.y;
    const int tid = ty * 32 + tx;
    const int r0 = 32 * by - 3;
    const int c0 = 64 * bx - 4;

    float f0[5], f1[7];
#pragma unroll
    for (int k = 0; k < 5; k++) f0[k] = __ldg(h0 + k);
#pragma unroll
    for (int k = 0; k < 7; k++) f1[k] = __ldg(h1 + k);

    // ---- phase 1 (scalar): fused load + row filter. 38 rows x 16 quad-tasks ----
    for (int idx = tid; idx < 38 * 16; idx += 256) {
        int rr = idx >> 4, q = idx & 15;
        int c = c0 + 4 * q;
        const T* rowp = xim + (long)refl(r0 + rr, W) * W;
        float w[12];
        if (c >= 0 && c + 11 < W) {
            load12(rowp, c, w);
        } else {
#pragma unroll
            for (int j = 0; j < 12; j++) w[j] = to_f(rowp[refl(c + j, W)]);
        }
        float o0[4], o1[4];
#pragma unroll
        for (int j = 0; j < 4; j++) {
            float s1 = 0.f;
#pragma unroll
            for (int k = 0; k < 7; k++) s1 += f1[k] * w[j + 1 + k];
            float s0 = 0.f;
#pragma unroll
            for (int k = 0; k < 5; k++) s0 += f0[k] * w[j + 2 + k];
            o0[j] = s0; o1[j] = s1;
        }
        ((float4*)slo[rr])[q] = make_float4(o0[0], o0[1], o0[2], o0[3]);
        ((float4*)shi[rr])[q] = make_float4(o1[0], o1[1], o1[2], o1[3]);
    }
    __syncthreads();

    // packed taps for the column filter
    u64 f0q[5], f1q[7];
#pragma unroll
    for (int k = 0; k < 5; k++) f0q[k] = bc2(f0[k]);
#pragma unroll
    for (int k = 0; k < 7; k++) f1q[k] = bc2(f1[k]);

    // ---- phase 2a: lo branch (ll + lh), packed, 2 out rows ----
    {
        u64 ll0[2] = {0,0}, ll1[2] = {0,0}, lh0[2] = {0,0}, lh1[2] = {0,0};
#pragma unroll
        for (int r = 0; r < 10; r++) {
            u64 l = ((const u64*)slo[4 * ty + r])[tx];
#pragma unroll
            for (int u = 0; u < 2; u++) {
                int idx = r - 2 * u;
                if (idx < 0 || idx > 7) continue;
                if (idx <= 6)             fmap(lh0[u], f1q[idx], l);
                if (idx >= 1)             fmap(lh1[u], f1q[idx-1], l);
                if (idx >= 1 && idx <= 5) fmap(ll0[u], f0q[idx-1], l);
                if (idx >= 2 && idx <= 6) fmap(ll1[u], f0q[idx-2], l);
            }
        }
#pragma unroll
        for (int u = 0; u < 2; u++) {
            float2 L0 = upk(ll0[u]), L1 = upk(ll1[u]);
            float2 G0 = upk(lh0[u]), G1 = upk(lh1[u]);
            float m0, m5;
            q2c_mags(G0.x, G0.y, G1.x, G1.y, m0, m5);
            wr.lo(u, L0, L1, m0, m5);
        }
    }
    // ---- phase 2b: hi branch (hl + hh), packed ----
    {
        u64 hl0[2] = {0,0}, hl1[2] = {0,0}, hh0[2] = {0,0}, hh1[2] = {0,0};
#pragma unroll
        for (int r = 0; r < 10; r++) {
            u64 h = ((const u64*)shi[4 * ty + r])[tx];
#pragma unroll
            for (int u = 0; u < 2; u++) {
                int idx = r - 2 * u;
                if (idx < 0 || idx > 7) continue;
                if (idx <= 6)             fmap(hh0[u], f1q[idx], h);
                if (idx >= 1)             fmap(hh1[u], f1q[idx-1], h);
                if (idx >= 1 && idx <= 5) fmap(hl0[u], f0q[idx-1], h);
                if (idx >= 2 && idx <= 6) fmap(hl1[u], f0q[idx-2], h);
            }
        }
#pragma unroll
        for (int u = 0; u < 2; u++) {
            float2 E0 = upk(hl0[u]), E1 = upk(hl1[u]);
            float2 G0 = upk(hh0[u]), G1 = upk(hh1[u]);
            float m1, m4, m2, m3;
            q2c_mags(G0.x, G0.y, G1.x, G1.y, m1, m4);
            q2c_mags(E0.x, E0.y, E1.x, E1.y, m2, m3);
            wr.hi(u, m1, m4, m2, m3);
        }
    }
}

// ---------------------------------------------------------------------------
// Stage A writer + kernel. Grid (8,16,96), block (32,8).
// ---------------------------------------------------------------------------
struct AWriter {
    __half* llp0;  // ll row 2*Ybase at px col (element units)
    __half* pb;    // p plane (b*18+ch), row Ybase, col Xp
    __device__ __forceinline__ void lo(int u, float2 a, float2 bq, float m0, float m5) {
        *(__half2*)(llp0 + u * 1024)       = __floats2half2_rn(a.x, a.y);
        *(__half2*)(llp0 + u * 1024 + 512) = __floats2half2_rn(bq.x, bq.y);
        pb[u * 256]               = __float2half_rn(m0);
        pb[u * 256 + 5L * 196608] = __float2half_rn(m5);
    }
    __device__ __forceinline__ void hi(int u, float m1, float m4, float m2, float m3) {
        pb[u * 256 + 1L * 196608] = __float2half_rn(m1);
        pb[u * 256 + 4L * 196608] = __float2half_rn(m4);
        pb[u * 256 + 2L * 196608] = __float2half_rn(m2);
        pb[u * 256 + 3L * 196608] = __float2half_rn(m3);
    }
};

__global__ __launch_bounds__(256, 4) void k_fusedA(
    const float* __restrict__ x,
    const float* __restrict__ h0, const float* __restrict__ h1,
    __half* __restrict__ ll, __half* __restrict__ p)
{
    const int bx = blockIdx.x, by = blockIdx.y, img = blockIdx.z;
    const int tx = threadIdx.x, ty = threadIdx.y;
    const int Ybase = 16 * by + 2 * ty;
    int b = img / 3, ch = img - 3 * b;

    AWriter wr;
    wr.llp0 = ll + (long)img * 262144 + (long)(2 * Ybase) * 512 + (64 * bx + 2 * tx);
    wr.pb   = p + ((long)b * 18 + ch) * 65536 + (long)Ybase * 256 + (32 * bx + tx);
    j1_core2<512>(x + (long)img * 262144, h0, h1, bx, by, wr);
}

// ---------------------------------------------------------------------------
// Stage C writer + kernel. Grid (4,8,576), block (32,8).
// ---------------------------------------------------------------------------
struct CWriter {
    float* zb;   // Z (b,ch) base, row Ybase, col Xp (fp32 output)
    int o1;
    __device__ __forceinline__ void lo(int u, float2 a, float2 bq, float m0, float m5) {
        float av = 0.25f * (a.x + a.y + bq.x + bq.y);
        zb[u * 128 + (long)(1 + o1) * 49152]  = av;
        zb[u * 128 + (long)(13 + o1) * 49152] = m0;
        zb[u * 128 + (long)(43 + o1) * 49152] = m5;
    }
    __device__ __forceinline__ void hi(int u, float m1, float m4, float m2, float m3) {
        zb[u * 128 + (long)(19 + o1) * 49152] = m1;
        zb[u * 128 + (long)(37 + o1) * 49152] = m4;
        zb[u * 128 + (long)(25 + o1) * 49152] = m2;
        zb[u * 128 + (long)(31 + o1) * 49152] = m3;
    }
};

__global__ __launch_bounds__(256, 4) void k_fusedC(
    const __half* __restrict__ p,
    const float* __restrict__ h0, const float* __restrict__ h1,
    float* __restrict__ Z)
{
    const int bx = blockIdx.x, by = blockIdx.y, img = blockIdx.z;
    const int tx = threadIdx.x, ty = threadIdx.y;
    const int Ybase = 16 * by + 2 * ty;
    int b = img / 18;
    int c18 = img - 18 * b;
    int o1 = c18 / 3;
    int ch = c18 - 3 * o1;

    CWriter wr;
    wr.zb = Z + ((long)b * 147 + ch) * 16384 + (long)Ybase * 128 + (32 * bx + tx);
    wr.o1 = o1;
    j1_core2<256>(p + (long)img * 65536, h0, h1, bx, by, wr);
}

// ---------------------------------------------------------------------------
// Stage B: fused (load + rowdfilt) -> smem -> coldfilt (2 out rows/thread)
// + q2c + avgpool, packed. Block (16,16): out tile 32Y x 16X. Grid (8,4,96).
// Reads fp16 ll, writes fp32 Z slots 0, 7..12.
// ---------------------------------------------------------------------------
__global__ __launch_bounds__(256, 4) void k_fusedB(
    const __half* __restrict__ ll,
    const float* __restrict__ h0a, const float* __restrict__ h0b,
    const float* __restrict__ h1a, const float* __restrict__ h1b,
    float* __restrict__ Z)
{
    __shared__ __align__(16) float sl2[144][32];
    __shared__ __align__(16) float sh2[144][32];

    const int bx = blockIdx.x, by = blockIdx.y, img = blockIdx.z;
    const int tx = threadIdx.x, ty = threadIdx.y;
    const int tid = ty * 16 + tx;
    const __half* lim = ll + (long)img * 262144;
    const int r0 = 128 * by - 8, c0 = 64 * bx - 8;

    float fa0[10], fb0[10], fa1[10], fb1[10];
#pragma unroll
    for (int k = 0; k < 10; k++) {
        fa0[k] = __ldg(h0a + k); fb0[k] = __ldg(h0b + k);
        fa1[k] = __ldg(h1a + k); fb1[k] = __ldg(h1b + k);
    }

    // ---- phase 1: fused load + rowdfilt, packed. 144 rows x 8 quad-tasks ----
    // w2[i] = (w[2i], w[2i+1]); operand for (j,k) = w2[2j+k].
    for (int idx = tid; idx < 144 * 8; idx += 256) {
        int rr = idx >> 3, qq = idx & 7;
        int c = c0 + 8 * qq;
        const __half* rowp = lim + (long)refl(r0 + rr, 512) * 512;
        u64 w2[12];
        if (c >= 0 && c + 23 < 512) {
#pragma unroll
            for (int j = 0; j < 3; j++) {
                uint4 v = *(const uint4*)(rowp + c + 8 * j);   // 8 halves
                const __half2* hv = (const __half2*)&v;
#pragma unroll
                for (int i = 0; i < 4; i++) {
                    float2 f = __half22float2(hv[i]);
                    w2[4*j + i] = pk2(f.x, f.y);
                }
            }
        } else {
            float w[24];
#pragma unroll
            for (int j = 0; j < 24; j++) w[j] = __half2float(rowp[refl(c + j, 512)]);
#pragma unroll
            for (int i = 0; i < 12; i++) w2[i] = pk2(w[2*i], w[2*i+1]);
        }
        u64 accL[2] = {0ull, 0ull}, accH[2] = {0ull, 0ull};
#pragma unroll
        for (int k = 0; k < 10; k++) {
            u64 cl = pk2(fb0[k], fa0[k]);
            u64 ch = pk2(fb1[k], fa1[k]);
#pragma unroll
            for (int j = 0; j < 2; j++) {
                fmap(accL[j], cl, w2[2*j + k]);
                fmap(accH[j], ch, w2[2*j + k]);
            }
        }
        float2 L0 = upk(accL[0]), L1 = upk(accL[1]);
        float2 H0 = upk(accH[0]), H1 = upk(accH[1]);
        ((float4*)sl2[rr])[qq] = make_float4(L0.x, L0.y, L1.x, L1.y);
        ((float4*)sh2[rr])[qq] = make_float4(H0.y, H0.x, H1.y, H1.x);
    }
    __syncthreads();

    const int Ybase = 32 * by + 2 * ty, X = 16 * bx + tx;
    int b = img / 3, ch = img - 3 * b;
    float* zb = Z + ((long)b * 147 + ch) * 16384 + ((long)Ybase * 128 + X);

    // ---- phase 2a: lo branch (ll2 + lh2), packed ----
    {
        u64 ll0[2] = {0,0}, ll1[2] = {0,0}, lh0[2] = {0,0}, lh1[2] = {0,0};
#pragma unroll
        for (int j = 0; j < 12; j++) {
            int lrE = 8 * ty + 2 * j, lrO = lrE + 1;
            u64 a = ((const u64*)sl2[lrE])[tx];
            u64 q = ((const u64*)sl2[lrO])[tx];
#pragma unroll
            for (int u = 0; u < 2; u++) {
                int k = j - 2 * u;
                if (k < 0 || k > 9) continue;
                fmap(ll0[u], bc2(fb0[k]), a);
                fmap(ll1[u], bc2(fa0[k]), q);
                fmap(lh0[u], bc2(fa1[k]), q);
                fmap(lh1[u], bc2(fb1[k]), a);
            }
        }
#pragma unroll
        for (int u = 0; u < 2; u++) {
            float2 L0 = upk(ll0[u]), L1 = upk(ll1[u]);
            float2 G0 = upk(lh0[u]), G1 = upk(lh1[u]);
            float s0v = 0.25f * (L0.x + L0.y + L1.x + L1.y);
            float m0, m5;
            q2c_mags(G0.x, G0.y, G1.x, G1.y, m0, m5);
            zb[u * 128] = s0v;
            zb[u * 128 + 7L  * 49152] = m0;
            zb[u * 128 + 12L * 49152] = m5;
        }
    }
    // ---- phase 2b: hi branch (hl2 + hh2), packed ----
    {
        u64 hl0[2] = {0,0}, hl1[2] = {0,0}, hh0[2] = {0,0}, hh1[2] = {0,0};
#pragma unroll
        for (int j = 0; j < 12; j++) {
            int lrE = 8 * ty + 2 * j, lrO = lrE + 1;
            u64 cv = ((const u64*)sh2[lrE])[tx];
            u64 dv = ((const u64*)sh2[lrO])[tx];
#pragma unroll
            for (int u = 0; u < 2; u++) {
                int k = j - 2 * u;
                if (k < 0 || k > 9) continue;
                fmap(hl0[u], bc2(fb0[k]), cv);
                fmap(hl1[u], bc2(fa0[k]), dv);
                fmap(hh0[u], bc2(fa1[k]), dv);
                fmap(hh1[u], bc2(fb1[k]), cv);
            }
        }
#pragma unroll
        for (int u = 0; u < 2; u++) {
            float2 E0 = upk(hl0[u]), E1 = upk(hl1[u]);
            float2 G0 = upk(hh0[u]), G1 = upk(hh1[u]);
            float m1, m4, m2, m3;
            q2c_mags(G0.x, G0.y, G1.x, G1.y, m1, m4);
            q2c_mags(E0.x, E0.y, E1.x, E1.y, m2, m3);
            zb[u * 128 + 8L  * 49152] = m1;
            zb[u * 128 + 11L * 49152] = m4;
            zb[u * 128 + 9L  * 49152] = m2;
            zb[u * 128 + 10L * 49152] = m3;
        }
    }
}

// ---------------------------------------------------------------------------
// Host launcher (graph-capturable)
// ---------------------------------------------------------------------------
extern "C" void kernel_launch(void* const* d_in, const int* in_sizes, int n_in,
                              void* d_out, int out_size)
{
    const float* x   = (const float*)d_in[0];
    const float* h0o = (const float*)d_in[1];
    const float* h1o = (const float*)d_in[2];
    const float* h0a = (const float*)d_in[3];
    const float* h0b = (const float*)d_in[4];
    const float* h1a = (const float*)d_in[5];
    const float* h1b = (const float*)d_in[6];
    float* Z = (float*)d_out;

    __half *ll, *p;
    cudaGetSymbolAddress((void**)&ll, g_ll);
    cudaGetSymbolAddress((void**)&p,  g_p);

    k_fusedA<<<dim3(8, 16, 96), dim3(32, 8)>>>(x, h0o, h1o, ll, p);
    k_fusedB<<<dim3(8, 4, 96),  dim3(16, 16)>>>(ll, h0a, h0b, h1a, h1b, Z);
    k_fusedC<<<dim3(4, 8, 576), dim3(32, 8)>>>(p, h0o, h1o, Z);
}

// round 15
// speedup vs baseline: 2.7890x; 1.1026x over previous
#include <cuda_runtime.h>
#include <cuda_fp16.h>

// ---------------------------------------------------------------------------
// ScatLayerj2: 2-level DTCWT scattering. Fused; fp16 intermediates; wide
// phase-1 tasks; 4-px phase-2. x (32,3,512,512) f32 -> Z (32,147,128,128) f32
// ---------------------------------------------------------------------------

typedef unsigned long long u64;

static __device__ __forceinline__ u64 pk2(float lo, float hi) {
    u64 r; asm("mov.b64 %0,{%1,%2};" : "=l"(r) : "f"(lo), "f"(hi)); return r;
}
static __device__ __forceinline__ float2 upk(u64 v) {
    float2 r; asm("mov.b64 {%0,%1},%2;" : "=f"(r.x), "=f"(r.y) : "l"(v)); return r;
}
static __device__ __forceinline__ void fmap(u64& d, u64 a, u64 b) {
    asm("fma.rn.f32x2 %0,%1,%2,%0;" : "+l"(d) : "l"(a), "l"(b));
}

static __device__ __forceinline__ int refl(int p, int l) {
    if (p < 0)  p = -1 - p;
    if (p >= l) p = 2 * l - 1 - p;
    return p;
}

static __device__ __forceinline__ float smag(float re, float im) {
    return sqrtf(re * re + im * im + 1e-4f) - 0.01f;
}

static __device__ __forceinline__ void q2c_mags(float v0x, float v0y, float v1x, float v1y,
                                                float& m_first, float& m_second) {
    const float s = 0.70710678118654752440f;
    float a = v0x * s, b = v0y * s, c = v1x * s, d = v1y * s;
    m_first  = smag(a - d, b + c);
    m_second = smag(a + d, b - c);
}

static __device__ __forceinline__ float to_f(float v)  { return v; }
static __device__ __forceinline__ float to_f(__half v) { return __half2float(v); }

// 16-wide window loaders (interior; c is a multiple of 4 elements)
static __device__ __forceinline__ void load16(const float* rowp, int c, float* w) {
#pragma unroll
    for (int j = 0; j < 4; j++) {
        float4 v = *(const float4*)(rowp + c + 4 * j);   // 16B at 16B-aligned (c%4==0)
        w[4*j] = v.x; w[4*j+1] = v.y; w[4*j+2] = v.z; w[4*j+3] = v.w;
    }
}
static __device__ __forceinline__ void load16(const __half* rowp, int c, float* w) {
    // c % 4 == 0 (elements) -> byte offset % 8 == 0: use 8-byte loads (uint2),
    // NOT uint4 (16-byte) which faults when c % 8 == 4.
#pragma unroll
    for (int j = 0; j < 4; j++) {
        uint2 v = *(const uint2*)(rowp + c + 4 * j);     // 4 halves
        const __half2* hv = (const __half2*)&v;
#pragma unroll
        for (int i = 0; i < 2; i++) {
            float2 f = __half22float2(hv[i]);
            w[4*j + 2*i] = f.x; w[4*j + 2*i + 1] = f.y;
        }
    }
}

// Scratch (fp16): ll (96*512*512) and p (576*256*256)
__device__ __align__(16) __half g_ll[25165824];
__device__ __align__(16) __half g_p [37748736];

// ---------------------------------------------------------------------------
// j1 fused core: (load + rowfilter, 8-wide tasks) -> smem lo/hi (38x128) ->
// split col filter, 4 px x 2 out rows per thread. Block (32,8).
// Out tile: 16 pair-rows x 64 pairs (128 lo-cols).
// ---------------------------------------------------------------------------
template<int W, typename T, class Writer>
static __device__ __forceinline__ void j1_core(
    const T* __restrict__ xim,
    const float* __restrict__ h0, const float* __restrict__ h1,
    int bx, int by, Writer& wr)
{
    __shared__ __align__(16) float slo[38][128];
    __shared__ __align__(16) float shi[38][128];

    const int tx = threadIdx.x, ty = threadIdx.y;
    const int tid = ty * 32 + tx;
    const int r0 = 32 * by - 3;
    const int c0 = 128 * bx - 4;

    float f0[5], f1[7];
#pragma unroll
    for (int k = 0; k < 5; k++) f0[k] = __ldg(h0 + k);
#pragma unroll
    for (int k = 0; k < 7; k++) f1[k] = __ldg(h1 + k);

    // ---- phase 1: fused load + row filter. 38 rows x 16 eight-wide tasks ----
    // out local col L = 8q+j; h1 taps -> w[j+1+k], h0 -> w[j+2+k]
    for (int idx = tid; idx < 38 * 16; idx += 256) {
        int rr = idx >> 4, q = idx & 15;
        int c = c0 + 8 * q;
        const T* rowp = xim + (long)refl(r0 + rr, W) * W;
        float w[16];
        if (c >= 0 && c + 15 < W) {
            load16(rowp, c, w);
        } else {
#pragma unroll
            for (int j = 0; j < 16; j++) w[j] = to_f(rowp[refl(c + j, W)]);
        }
        float o0[8], o1[8];
#pragma unroll
        for (int j = 0; j < 8; j++) {
            float s1 = 0.f;
#pragma unroll
            for (int k = 0; k < 7; k++) s1 += f1[k] * w[j + 1 + k];
            float s0 = 0.f;
#pragma unroll
            for (int k = 0; k < 5; k++) s0 += f0[k] * w[j + 2 + k];
            o0[j] = s0; o1[j] = s1;
        }
        ((float4*)slo[rr])[2*q]   = make_float4(o0[0], o0[1], o0[2], o0[3]);
        ((float4*)slo[rr])[2*q+1] = make_float4(o0[4], o0[5], o0[6], o0[7]);
        ((float4*)shi[rr])[2*q]   = make_float4(o1[0], o1[1], o1[2], o1[3]);
        ((float4*)shi[rr])[2*q+1] = make_float4(o1[4], o1[5], o1[6], o1[7]);
    }
    __syncthreads();

    // ---- phase 2a: lo branch (ll + lh), 4 px, 2 out rows, stream 10 rows ----
    {
        float4 ll0[2], ll1[2], lh0[2], lh1[2];
#pragma unroll
        for (int u = 0; u < 2; u++) {
            ll0[u] = make_float4(0,0,0,0); ll1[u] = make_float4(0,0,0,0);
            lh0[u] = make_float4(0,0,0,0); lh1[u] = make_float4(0,0,0,0);
        }
#pragma unroll
        for (int r = 0; r < 10; r++) {
            float4 l = ((const float4*)slo[4 * ty + r])[tx];
#pragma unroll
            for (int u = 0; u < 2; u++) {
                int idx = r - 2 * u;
                if (idx < 0 || idx > 7) continue;
                if (idx <= 6) { float c = f1[idx];
                    lh0[u].x += c*l.x; lh0[u].y += c*l.y; lh0[u].z += c*l.z; lh0[u].w += c*l.w; }
                if (idx >= 1) { float c = f1[idx-1];
                    lh1[u].x += c*l.x; lh1[u].y += c*l.y; lh1[u].z += c*l.z; lh1[u].w += c*l.w; }
                if (idx >= 1 && idx <= 5) { float c = f0[idx-1];
                    ll0[u].x += c*l.x; ll0[u].y += c*l.y; ll0[u].z += c*l.z; ll0[u].w += c*l.w; }
                if (idx >= 2 && idx <= 6) { float c = f0[idx-2];
                    ll1[u].x += c*l.x; ll1[u].y += c*l.y; ll1[u].z += c*l.z; ll1[u].w += c*l.w; }
            }
        }
#pragma unroll
        for (int u = 0; u < 2; u++) {
            float2 m0, m5;
            q2c_mags(lh0[u].x, lh0[u].y, lh1[u].x, lh1[u].y, m0.x, m5.x);
            q2c_mags(lh0[u].z, lh0[u].w, lh1[u].z, lh1[u].w, m0.y, m5.y);
            wr.lo(u, ll0[u], ll1[u], m0, m5);
        }
    }
    // ---- phase 2b: hi branch (hl + hh) ----
    {
        float4 hl0[2], hl1[2], hh0[2], hh1[2];
#pragma unroll
        for (int u = 0; u < 2; u++) {
            hl0[u] = make_float4(0,0,0,0); hl1[u] = make_float4(0,0,0,0);
            hh0[u] = make_float4(0,0,0,0); hh1[u] = make_float4(0,0,0,0);
        }
#pragma unroll
        for (int r = 0; r < 10; r++) {
            float4 h = ((const float4*)shi[4 * ty + r])[tx];
#pragma unroll
            for (int u = 0; u < 2; u++) {
                int idx = r - 2 * u;
                if (idx < 0 || idx > 7) continue;
                if (idx <= 6) { float c = f1[idx];
                    hh0[u].x += c*h.x; hh0[u].y += c*h.y; hh0[u].z += c*h.z; hh0[u].w += c*h.w; }
                if (idx >= 1) { float c = f1[idx-1];
                    hh1[u].x += c*h.x; hh1[u].y += c*h.y; hh1[u].z += c*h.z; hh1[u].w += c*h.w; }
                if (idx >= 1 && idx <= 5) { float c = f0[idx-1];
                    hl0[u].x += c*h.x; hl0[u].y += c*h.y; hl0[u].z += c*h.z; hl0[u].w += c*h.w; }
                if (idx >= 2 && idx <= 6) { float c = f0[idx-2];
                    hl1[u].x += c*h.x; hl1[u].y += c*h.y; hl1[u].z += c*h.z; hl1[u].w += c*h.w; }
            }
        }
#pragma unroll
        for (int u = 0; u < 2; u++) {
            float2 m1, m4, m2, m3;
            q2c_mags(hh0[u].x, hh0[u].y, hh1[u].x, hh1[u].y, m1.x, m4.x);
            q2c_mags(hh0[u].z, hh0[u].w, hh1[u].z, hh1[u].w, m1.y, m4.y);
            q2c_mags(hl0[u].x, hl0[u].y, hl1[u].x, hl1[u].y, m2.x, m3.x);
            q2c_mags(hl0[u].z, hl0[u].w, hl1[u].z, hl1[u].w, m2.y, m3.y);
            wr.hi(u, m1, m4, m2, m3);
        }
    }
}

static __device__ __forceinline__ uint2 f4_to_h4(float4 v) {
    __half2 a = __floats2half2_rn(v.x, v.y);
    __half2 b = __floats2half2_rn(v.z, v.w);
    uint2 r;
    r.x = *(unsigned*)&a;
    r.y = *(unsigned*)&b;
    return r;
}

// ---------------------------------------------------------------------------
// Stage A writer + kernel. Grid (4,16,96), block (32,8).
// Ybase = 16by + 2ty; ll px col = 128bx + 4tx; p pair col = 64bx + 2tx.
// ---------------------------------------------------------------------------
struct AWriter {
    __half* llp0;
    __half* pb;
    __device__ __forceinline__ void lo(int u, float4 a, float4 bq, float2 m0, float2 m5) {
        *(uint2*)(llp0 + u * 1024)       = f4_to_h4(a);   // 8B at 8B-aligned
        *(uint2*)(llp0 + u * 1024 + 512) = f4_to_h4(bq);
        *(__half2*)(pb + u * 256)               = __floats2half2_rn(m0.x, m0.y);
        *(__half2*)(pb + u * 256 + 5L * 196608) = __floats2half2_rn(m5.x, m5.y);
    }
    __device__ __forceinline__ void hi(int u, float2 m1, float2 m4, float2 m2, float2 m3) {
        *(__half2*)(pb + u * 256 + 1L * 196608) = __floats2half2_rn(m1.x, m1.y);
        *(__half2*)(pb + u * 256 + 4L * 196608) = __floats2half2_rn(m4.x, m4.y);
        *(__half2*)(pb + u * 256 + 2L * 196608) = __floats2half2_rn(m2.x, m2.y);
        *(__half2*)(pb + u * 256 + 3L * 196608) = __floats2half2_rn(m3.x, m3.y);
    }
};

__global__ __launch_bounds__(256, 4) void k_fusedA(
    const float* __restrict__ x,
    const float* __restrict__ h0, const float* __restrict__ h1,
    __half* __restrict__ ll, __half* __restrict__ p)
{
    const int bx = blockIdx.x, by = blockIdx.y, img = blockIdx.z;
    const int tx = threadIdx.x, ty = threadIdx.y;
    const int Ybase = 16 * by + 2 * ty;
    int b = img / 3, ch = img - 3 * b;

    AWriter wr;
    wr.llp0 = ll + (long)img * 262144 + (long)(2 * Ybase) * 512 + (128 * bx + 4 * tx);
    wr.pb   = p + ((long)b * 18 + ch) * 65536 + (long)Ybase * 256 + (64 * bx + 2 * tx);
    j1_core<512>(x + (long)img * 262144, h0, h1, bx, by, wr);
}

// ---------------------------------------------------------------------------
// Stage C writer + kernel. Grid (2,8,576), block (32,8).
// ---------------------------------------------------------------------------
struct CWriter {
    float* zb;
    int o1;
    __device__ __forceinline__ void st2(long off, float2 v) {
        __stcs((float2*)(zb + off), v);
    }
    __device__ __forceinline__ void lo(int u, float4 a, float4 bq, float2 m0, float2 m5) {
        float2 av = make_float2(0.25f * (a.x + a.y + bq.x + bq.y),
                                0.25f * (a.z + a.w + bq.z + bq.w));
        st2(u * 128 + (long)(1 + o1) * 49152, av);
        st2(u * 128 + (long)(13 + o1) * 49152, m0);
        st2(u * 128 + (long)(43 + o1) * 49152, m5);
    }
    __device__ __forceinline__ void hi(int u, float2 m1, float2 m4, float2 m2, float2 m3) {
        st2(u * 128 + (long)(19 + o1) * 49152, m1);
        st2(u * 128 + (long)(37 + o1) * 49152, m4);
        st2(u * 128 + (long)(25 + o1) * 49152, m2);
        st2(u * 128 + (long)(31 + o1) * 49152, m3);
    }
};

__global__ __launch_bounds__(256, 4) void k_fusedC(
    const __half* __restrict__ p,
    const float* __restrict__ h0, const float* __restrict__ h1,
    float* __restrict__ Z)
{
    const int bx = blockIdx.x, by = blockIdx.y, img = blockIdx.z;
    const int tx = threadIdx.x, ty = threadIdx.y;
    const int Ybase = 16 * by + 2 * ty;
    int b = img / 18;
    int c18 = img - 18 * b;
    int o1 = c18 / 3;
    int ch = c18 - 3 * o1;

    CWriter wr;
    wr.zb = Z + ((long)b * 147 + ch) * 16384 + (long)Ybase * 128 + (64 * bx + 2 * tx);
    wr.o1 = o1;
    j1_core<256>(p + (long)img * 65536, h0, h1, bx, by, wr);
}

// ---------------------------------------------------------------------------
// Stage B: fused (load + rowdfilt) -> smem -> coldfilt (2 out rows/thread)
// + q2c + avgpool, packed. Block (16,16): out tile 32Y x 16X. Grid (8,4,96).
// Reads fp16 ll, writes fp32 Z slots 0, 7..12 (streaming).
// ---------------------------------------------------------------------------
__global__ __launch_bounds__(256, 4) void k_fusedB(
    const __half* __restrict__ ll,
    const float* __restrict__ h0a, const float* __restrict__ h0b,
    const float* __restrict__ h1a, const float* __restrict__ h1b,
    float* __restrict__ Z)
{
    __shared__ __align__(16) float sl2[144][32];
    __shared__ __align__(16) float sh2[144][32];

    const int bx = blockIdx.x, by = blockIdx.y, img = blockIdx.z;
    const int tx = threadIdx.x, ty = threadIdx.y;
    const int tid = ty * 16 + tx;
    const __half* lim = ll + (long)img * 262144;
    const int r0 = 128 * by - 8, c0 = 64 * bx - 8;

    float fa0[10], fb0[10], fa1[10], fb1[10];
#pragma unroll
    for (int k = 0; k < 10; k++) {
        fa0[k] = __ldg(h0a + k); fb0[k] = __ldg(h0b + k);
        fa1[k] = __ldg(h1a + k); fb1[k] = __ldg(h1b + k);
    }

    // ---- phase 1: fused load + rowdfilt, packed. 144 rows x 8 quad-tasks ----
    // c = c0 + 8*qq is a multiple of 8 halves -> 16B-aligned uint4 loads OK.
    for (int idx = tid; idx < 144 * 8; idx += 256) {
        int rr = idx >> 3, qq = idx & 7;
        int c = c0 + 8 * qq;
        const __half* rowp = lim + (long)refl(r0 + rr, 512) * 512;
        u64 w2[12];
        if (c >= 0 && c + 23 < 512) {
#pragma unroll
            for (int j = 0; j < 3; j++) {
                uint4 v = *(const uint4*)(rowp + c + 8 * j);
                const __half2* hv = (const __half2*)&v;
#pragma unroll
                for (int i = 0; i < 4; i++) {
                    float2 f = __half22float2(hv[i]);
                    w2[4*j + i] = pk2(f.x, f.y);
                }
            }
        } else {
            float w[24];
#pragma unroll
            for (int j = 0; j < 24; j++) w[j] = __half2float(rowp[refl(c + j, 512)]);
#pragma unroll
            for (int i = 0; i < 12; i++) w2[i] = pk2(w[2*i], w[2*i+1]);
        }
        u64 accL[2] = {0ull, 0ull}, accH[2] = {0ull, 0ull};
#pragma unroll
        for (int k = 0; k < 10; k++) {
            u64 cl = pk2(fb0[k], fa0[k]);
            u64 ch = pk2(fb1[k], fa1[k]);
#pragma unroll
            for (int j = 0; j < 2; j++) {
                fmap(accL[j], cl, w2[2*j + k]);
                fmap(accH[j], ch, w2[2*j + k]);
            }
        }
        float2 L0 = upk(accL[0]), L1 = upk(accL[1]);
        float2 H0 = upk(accH[0]), H1 = upk(accH[1]);
        ((float4*)sl2[rr])[qq] = make_float4(L0.x, L0.y, L1.x, L1.y);
        ((float4*)sh2[rr])[qq] = make_float4(H0.y, H0.x, H1.y, H1.x);
    }
    __syncthreads();

    const int Ybase = 32 * by + 2 * ty, X = 16 * bx + tx;
    int b = img / 3, ch = img - 3 * b;
    float* zb = Z + ((long)b * 147 + ch) * 16384 + ((long)Ybase * 128 + X);

    // ---- phase 2a: lo branch (ll2 + lh2), packed ----
    {
        u64 ll0[2] = {0,0}, ll1[2] = {0,0}, lh0[2] = {0,0}, lh1[2] = {0,0};
#pragma unroll
        for (int j = 0; j < 12; j++) {
            int lrE = 8 * ty + 2 * j, lrO = lrE + 1;
            u64 a = ((const u64*)sl2[lrE])[tx];
            u64 q = ((const u64*)sl2[lrO])[tx];
#pragma unroll
            for (int u = 0; u < 2; u++) {
                int k = j - 2 * u;
                if (k < 0 || k > 9) continue;
                fmap(ll0[u], pk2(fb0[k], fb0[k]), a);
                fmap(ll1[u], pk2(fa0[k], fa0[k]), q);
                fmap(lh0[u], pk2(fa1[k], fa1[k]), q);
                fmap(lh1[u], pk2(fb1[k], fb1[k]), a);
            }
        }
#pragma unroll
        for (int u = 0; u < 2; u++) {
            float2 L0 = upk(ll0[u]), L1 = upk(ll1[u]);
            float2 G0 = upk(lh0[u]), G1 = upk(lh1[u]);
            float s0v = 0.25f * (L0.x + L0.y + L1.x + L1.y);
            float m0, m5;
            q2c_mags(G0.x, G0.y, G1.x, G1.y, m0, m5);
            __stcs(zb + u * 128, s0v);
            __stcs(zb + u * 128 + 7L  * 49152, m0);
            __stcs(zb + u * 128 + 12L * 49152, m5);
        }
    }
    // ---- phase 2b: hi branch (hl2 + hh2), packed ----
    {
        u64 hl0[2] = {0,0}, hl1[2] = {0,0}, hh0[2] = {0,0}, hh1[2] = {0,0};
#pragma unroll
        for (int j = 0; j < 12; j++) {
            int lrE = 8 * ty + 2 * j, lrO = lrE + 1;
            u64 cv = ((const u64*)sh2[lrE])[tx];
            u64 dv = ((const u64*)sh2[lrO])[tx];
#pragma unroll
            for (int u = 0; u < 2; u++) {
                int k = j - 2 * u;
                if (k < 0 || k > 9) continue;
                fmap(hl0[u], pk2(fb0[k], fb0[k]), cv);
                fmap(hl1[u], pk2(fa0[k], fa0[k]), dv);
                fmap(hh0[u], pk2(fa1[k], fa1[k]), dv);
                fmap(hh1[u], pk2(fb1[k], fb1[k]), cv);
            }
        }
#pragma unroll
        for (int u = 0; u < 2; u++) {
            float2 E0 = upk(hl0[u]), E1 = upk(hl1[u]);
            float2 G0 = upk(hh0[u]), G1 = upk(hh1[u]);
            float m1, m4, m2, m3;
            q2c_mags(G0.x, G0.y, G1.x, G1.y, m1, m4);
            q2c_mags(E0.x, E0.y, E1.x, E1.y, m2, m3);
            __stcs(zb + u * 128 + 8L  * 49152, m1);
            __stcs(zb + u * 128 + 11L * 49152, m4);
            __stcs(zb + u * 128 + 9L  * 49152, m2);
            __stcs(zb + u * 128 + 10L * 49152, m3);
        }
    }
}

// ---------------------------------------------------------------------------
// Host launcher (graph-capturable)
// ---------------------------------------------------------------------------
extern "C" void kernel_launch(void* const* d_in, const int* in_sizes, int n_in,
                              void* d_out, int out_size)
{
    const float* x   = (const float*)d_in[0];
    const float* h0o = (const float*)d_in[1];
    const float* h1o = (const float*)d_in[2];
    const float* h0a = (const float*)d_in[3];
    const float* h0b = (const float*)d_in[4];
    const float* h1a = (const float*)d_in[5];
    const float* h1b = (const float*)d_in[6];
    float* Z = (float*)d_out;

    __half *ll, *p;
    cudaGetSymbolAddress((void**)&ll, g_ll);
    cudaGetSymbolAddress((void**)&p,  g_p);

    k_fusedA<<<dim3(4, 16, 96), dim3(32, 8)>>>(x, h0o, h1o, ll, p);
    k_fusedB<<<dim3(8, 4, 96),  dim3(16, 16)>>>(ll, h0a, h0b, h1a, h1b, Z);
    k_fusedC<<<dim3(2, 8, 576), dim3(32, 8)>>>(p, h0o, h1o, Z);
}